// round 4
// baseline (speedup 1.0000x reference)
#include <cuda_runtime.h>
#include <cuda_bf16.h>

// ---------------------------------------------------------------------------
// L=256, B=32, D_MODEL=512, N_HEAD=8, D_HEAD=64, 2m=512, CHUNK=64
// causal fast-weight sum == masked quadratic attention:
//   S[t,s] = qf_t . kf_s (s<=t), out_t = S @ v, denom_t = row-sum(S)
// NOTE: device globals are NEVER passed as kernel arguments from host code
// (host-side symbol address is the host shadow; on GB300/ATS the GPU silently
// dereferences it -> writes land in host memory). All global-array binding
// happens inside device code.
// ---------------------------------------------------------------------------
#define ROWS 8192          // L*B
#define BH 256             // B*NHEAD

// ------------------------- scratch (device globals) ------------------------
__device__ float g_qkv[ROWS * 2048];          // [l*32+b, 2048]
__device__ float g_qf [BH * 256 * 512];       // [(b*8+h)*256 + l, 512]
__device__ float g_kf [BH * 256 * 512];
__device__ float g_v  [BH * 256 * 64];
__device__ float g_ai [ROWS * 512];           // attn output in [l,b,e] layout
__device__ float g_y  [ROWS * 512];           // w_o GEMM result

// ------------------------- block sum reduction ------------------------------
template<int NW>
__device__ __forceinline__ float block_sum(float v, float* red) {
    #pragma unroll
    for (int o = 16; o; o >>= 1) v += __shfl_xor_sync(0xffffffffu, v, o);
    if ((threadIdx.x & 31) == 0) red[threadIdx.x >> 5] = v;
    __syncthreads();
    if (threadIdx.x < 32) {
        float t = (threadIdx.x < NW) ? red[threadIdx.x] : 0.f;
        #pragma unroll
        for (int o = 16; o; o >>= 1) t += __shfl_xor_sync(0xffffffffu, t, o);
        if (threadIdx.x == 0) red[0] = t;
    }
    __syncthreads();
    float r = red[0];
    __syncthreads();
    return r;
}

// ------------------------- 128x128x8 SGEMM core -----------------------------
// C[M,N] = A[M,K] @ B[K,N], row-major, M%128==0, N%128==0, K%8==0.
// Called from __global__ wrappers so device-global pointers are formed in
// device code.
__device__ __forceinline__ void sgemm_body(
    const float* __restrict__ A, const float* __restrict__ B,
    float* __restrict__ C, int N, int K)
{
    __shared__ float As[8][128];
    __shared__ float Bs[8][128];
    int tid = threadIdx.x;
    int bm = blockIdx.y * 128, bn = blockIdx.x * 128;
    int la_r = tid >> 1;
    int la_c = (tid & 1) * 4;
    int lb_r = tid >> 5;
    int lb_c = (tid & 31) * 4;
    int tr = (tid >> 4) * 8;
    int tc = (tid & 15) * 8;
    float acc[8][8];
    #pragma unroll
    for (int i = 0; i < 8; i++)
        #pragma unroll
        for (int j = 0; j < 8; j++) acc[i][j] = 0.f;

    for (int k0 = 0; k0 < K; k0 += 8) {
        float4 a = *(const float4*)&A[(bm + la_r) * K + k0 + la_c];
        As[la_c + 0][la_r] = a.x; As[la_c + 1][la_r] = a.y;
        As[la_c + 2][la_r] = a.z; As[la_c + 3][la_r] = a.w;
        *(float4*)&Bs[lb_r][lb_c] = *(const float4*)&B[(k0 + lb_r) * N + bn + lb_c];
        __syncthreads();
        #pragma unroll
        for (int k = 0; k < 8; k++) {
            float ar[8], br[8];
            #pragma unroll
            for (int i = 0; i < 8; i++) ar[i] = As[k][tr + i];
            #pragma unroll
            for (int j = 0; j < 8; j++) br[j] = Bs[k][tc + j];
            #pragma unroll
            for (int i = 0; i < 8; i++)
                #pragma unroll
                for (int j = 0; j < 8; j++) acc[i][j] += ar[i] * br[j];
        }
        __syncthreads();
    }
    #pragma unroll
    for (int i = 0; i < 8; i++)
        #pragma unroll
        for (int j = 0; j < 8; j += 4)
            *(float4*)&C[(bm + tr + i) * N + bn + tc + j] =
                make_float4(acc[i][j], acc[i][j+1], acc[i][j+2], acc[i][j+3]);
}

// qkv projection: g_qkv = h @ w_qkv   [8192,512]@[512,2048]
__global__ __launch_bounds__(256) void sgemm_qkv(
    const float* __restrict__ h, const float* __restrict__ wqkv)
{
    sgemm_body(h, wqkv, g_qkv, 2048, 512);
}

// output projection: g_y = g_ai @ w_o   [8192,512]@[512,512]
__global__ __launch_bounds__(256) void sgemm_wo(const float* __restrict__ wo)
{
    sgemm_body(g_ai, wo, g_y, 512, 512);
}

// ------------------------- FAVOR+ features ---------------------------------
// grid (4, 256): blockIdx.y = bh (=b*8+h), blockIdx.x = 64-row group, 256 thr.
// Normalized feature = softmax over concat([xp, -xp]) (the -half and -max
// shifts of the reference cancel exactly in the sum-normalization).
__global__ __launch_bounds__(256) void feat_kernel(
    const float* __restrict__ proj, const float* __restrict__ pi0,
    const float* __restrict__ pi1)
{
    extern __shared__ float sm[];
    float* proj_s = sm;              // 16384 floats
    float* xrow   = sm + 16384;      // 256
    float* red    = sm + 16640;      // 32
    int tid = threadIdx.x;
    int lc  = blockIdx.x;
    int bh  = blockIdx.y;
    int hh  = bh & 7, b = bh >> 3;
    for (int i = tid; i < 16384; i += 256) proj_s[i] = proj[i];
    const float C = 0.3535533905932738f;   // 64^-0.25

    for (int ll = 0; ll < 64; ll++) {
        int l = lc * 64 + ll;
        __syncthreads();
        float val = g_qkv[(l * 32 + b) * 2048 + hh * 256 + tid];
        xrow[tid] = val;
        if (tid >= 192) g_v[(bh * 256 + l) * 64 + tid - 192] = val;
        __syncthreads();

        float xq = 0.f, x1 = 0.f, x2 = 0.f;
        #pragma unroll 8
        for (int d = 0; d < 64; d++) {
            float p = proj_s[d * 256 + tid];
            xq += xrow[d]       * p;
            x1 += xrow[64 + d]  * p;
            x2 += xrow[128 + d] * p;
        }
        xq = fminf(fmaxf(xq * C,        -30.f), 30.f);
        x1 = fminf(fmaxf(x1 * C,        -30.f), 30.f);
        x2 = fminf(fmaxf(x2 * C * 0.7f, -30.f), 30.f);

        float eqp = __expf(xq), eqm = __expf(-xq);
        float sq  = block_sum<8>(eqp + eqm, red);
        float invq = 1.f / sq;
        float* qd = g_qf + (bh * 256 + l) * 512;
        qd[tid] = eqp * invq; qd[256 + tid] = eqm * invq;

        float e1p = __expf(x1), e1m = __expf(-x1);
        float s1  = block_sum<8>(e1p + e1m, red);
        float inv1 = 1.f / s1;

        float e2p = __expf(x2), e2m = __expf(-x2);
        float s2  = block_sum<8>(e2p + e2m, red);
        float inv2 = 1.f / s2;

        float p0 = pi0[hh * 256 + l], p1v = pi1[hh * 256 + l];
        float* kd = g_kf + (bh * 256 + l) * 512;
        kd[tid]       = e1p * inv1 * p0 + e2p * inv2 * p1v;
        kd[256 + tid] = e1m * inv1 * p0 + e2m * inv2 * p1v;
    }
}

// ------------------------- masked quadratic attention ----------------------
// grid (4, 256): blockIdx.x = t-chunk (64 rows), blockIdx.y = bh. 256 threads
// as 16x16, each owning a 4x4 micro-tile.
__global__ __launch_bounds__(256) void attn_kernel() {
    extern __shared__ float sm[];
    float* A  = sm;            // 64*65: Q slice, then reused as S tile
    float* Ks = sm + 4160;     // 64*65
    float* Vs = sm + 8320;     // 64*64
    float* ds = sm + 12416;    // 64 denominators
    int tc = blockIdx.x, bh = blockIdx.y;
    int tid = threadIdx.x;
    int ty = tid >> 4, tx = tid & 15;
    int hh = bh & 7, b = bh >> 3;
    const float* qfp = g_qf + bh * 256 * 512;
    const float* kfp = g_kf + bh * 256 * 512;
    const float* vp  = g_v  + bh * 256 * 64;

    float out_acc[4][4];
    #pragma unroll
    for (int i = 0; i < 4; i++)
        #pragma unroll
        for (int j = 0; j < 4; j++) out_acc[i][j] = 0.f;
    if (tid < 64) ds[tid] = 0.f;

    for (int sc = 0; sc <= tc; sc++) {
        __syncthreads();                        // prev PV reads of A/Vs done
        for (int i = tid; i < 4096; i += 256)
            Vs[i] = vp[sc * 4096 + i];

        float s_acc[4][4];
        #pragma unroll
        for (int i = 0; i < 4; i++)
            #pragma unroll
            for (int j = 0; j < 4; j++) s_acc[i][j] = 0.f;

        for (int ks = 0; ks < 8; ks++) {
            __syncthreads();                    // prev readers of A/Ks done
            for (int i = tid; i < 4096; i += 256) {
                int r = i >> 6, f = i & 63;
                A [r * 65 + f] = qfp[(tc * 64 + r) * 512 + ks * 64 + f];
                Ks[r * 65 + f] = kfp[(sc * 64 + r) * 512 + ks * 64 + f];
            }
            __syncthreads();
            #pragma unroll 4
            for (int f = 0; f < 64; f++) {
                float qv[4], kv[4];
                #pragma unroll
                for (int i = 0; i < 4; i++) qv[i] = A [(4 * ty + i) * 65 + f];
                #pragma unroll
                for (int j = 0; j < 4; j++) kv[j] = Ks[(4 * tx + j) * 65 + f];
                #pragma unroll
                for (int i = 0; i < 4; i++)
                    #pragma unroll
                    for (int j = 0; j < 4; j++) s_acc[i][j] += qv[i] * kv[j];
            }
        }
        __syncthreads();                        // done reading A as Q
        #pragma unroll
        for (int i = 0; i < 4; i++)
            #pragma unroll
            for (int j = 0; j < 4; j++) {
                float v = s_acc[i][j];
                if (sc == tc && (4 * tx + j) > (4 * ty + i)) v = 0.f;
                A[(4 * ty + i) * 65 + (4 * tx + j)] = v;
            }
        __syncthreads();                        // S tile published
        if (tid < 64) {
            float t = 0.f;
            #pragma unroll 8
            for (int s = 0; s < 64; s++) t += A[tid * 65 + s];
            ds[tid] += t;
        }
        #pragma unroll 2
        for (int s = 0; s < 64; s++) {
            float sv[4];
            #pragma unroll
            for (int i = 0; i < 4; i++) sv[i] = A[(4 * ty + i) * 65 + s];
            #pragma unroll
            for (int j = 0; j < 4; j++) {
                float vv = Vs[s * 64 + 4 * tx + j];
                #pragma unroll
                for (int i = 0; i < 4; i++) out_acc[i][j] += sv[i] * vv;
            }
        }
    }
    __syncthreads();                            // ds complete
    #pragma unroll
    for (int i = 0; i < 4; i++) {
        float den = ds[4 * ty + i] + 1e-5f;
        float inv = 0.125f / den;
        int l = tc * 64 + 4 * ty + i;
        #pragma unroll
        for (int j = 0; j < 4; j++)
            g_ai[(l * 32 + b) * 512 + hh * 64 + 4 * tx + j] = out_acc[i][j] * inv;
    }
}

// ------------------------- residual + LayerNorm ----------------------------
__global__ __launch_bounds__(512) void ln_kernel(
    const float* __restrict__ hin, const float* __restrict__ gamma,
    const float* __restrict__ beta, float* __restrict__ out)
{
    __shared__ float red[32];
    int r = blockIdx.x, j = threadIdx.x;
    float x = g_y[r * 512 + j] + hin[r * 512 + j];
    float s1 = block_sum<16>(x, red);
    float mu = s1 * (1.f / 512.f);
    float d = x - mu;
    float s2 = block_sum<16>(d * d, red);
    float rstd = rsqrtf(s2 * (1.f / 512.f) + 1e-5f);
    out[r * 512 + j] = d * rstd * gamma[j] + beta[j];
}

// ------------------------- launch ------------------------------------------
extern "C" void kernel_launch(void* const* d_in, const int* in_sizes, int n_in,
                              void* d_out, int out_size) {
    const float* h     = (const float*)d_in[0];
    const float* wqkv  = (const float*)d_in[1];
    const float* wo    = (const float*)d_in[2];
    const float* gamma = (const float*)d_in[3];
    const float* beta  = (const float*)d_in[4];
    const float* pi0   = (const float*)d_in[5];
    const float* pi1   = (const float*)d_in[6];
    const float* proj  = (const float*)d_in[7];

    const int FEAT_SMEM = (16384 + 256 + 32) * 4;              // 66,688 B
    const int ATTN_SMEM = (4160 + 4160 + 4096 + 64) * 4;       // 49,920 B
    cudaFuncSetAttribute(feat_kernel, cudaFuncAttributeMaxDynamicSharedMemorySize, FEAT_SMEM);
    cudaFuncSetAttribute(attn_kernel, cudaFuncAttributeMaxDynamicSharedMemorySize, ATTN_SMEM);

    sgemm_qkv<<<dim3(16, 64), 256>>>(h, wqkv);
    feat_kernel<<<dim3(4, 256), 256, FEAT_SMEM>>>(proj, pi0, pi1);
    attn_kernel<<<dim3(4, 256), 256, ATTN_SMEM>>>();
    sgemm_wo<<<dim3(4, 64), 256>>>(wo);
    ln_kernel<<<8192, 512>>>(h, gamma, beta, (float*)d_out);
}

// round 7
// speedup vs baseline: 1.6889x; 1.6889x over previous
#include <cuda_runtime.h>
#include <cuda_bf16.h>
#include <cstdint>

// ---------------------------------------------------------------------------
// L=256, B=32, D_MODEL=512, N_HEAD=8, D_HEAD=64, 2m=512
// Tensor path via baseline mma.sync (m16n8k16 bf16) — tcgen05 is 'a'-feature
// gated and the harness builds for plain sm_103.
// Device globals only bound inside device code (GB300/ATS pitfall).
// ---------------------------------------------------------------------------
#define ROWS 8192
#define BH 256

__device__ float          g_qkv[ROWS * 2048];        // fp32 qkv output
__device__ __nv_bfloat16  g_hb [ROWS * 512];         // h in bf16
__device__ __nv_bfloat16  g_wqkvT[2048 * 512];       // wqkv^T bf16 [N,K]
__device__ __nv_bfloat16  g_woT [512 * 512];         // wo^T bf16 [N,K]
__device__ __nv_bfloat16  g_qf_b[BH * 256 * 512];    // features bf16
__device__ __nv_bfloat16  g_kf_b[BH * 256 * 512];
__device__ float          g_v  [BH * 256 * 64];
__device__ __nv_bfloat16  g_ai_b[ROWS * 512];        // attn out bf16 [l*32+b,512]
__device__ float          g_y  [ROWS * 512];

// ------------------------- mma.sync helper ----------------------------------
__device__ __forceinline__ void mma16816(float c[4],
    uint32_t a0, uint32_t a1, uint32_t a2, uint32_t a3,
    uint32_t b0, uint32_t b1)
{
    asm volatile(
        "mma.sync.aligned.m16n8k16.row.col.f32.bf16.bf16.f32 "
        "{%0,%1,%2,%3}, {%4,%5,%6,%7}, {%8,%9}, {%0,%1,%2,%3};"
        : "+f"(c[0]), "+f"(c[1]), "+f"(c[2]), "+f"(c[3])
        : "r"(a0), "r"(a1), "r"(a2), "r"(a3), "r"(b0), "r"(b1));
}

// ------------------------- block sum reduction ------------------------------
template<int NW>
__device__ __forceinline__ float block_sum(float v, float* red) {
    #pragma unroll
    for (int o = 16; o; o >>= 1) v += __shfl_xor_sync(0xffffffffu, v, o);
    if ((threadIdx.x & 31) == 0) red[threadIdx.x >> 5] = v;
    __syncthreads();
    if (threadIdx.x < 32) {
        float t = (threadIdx.x < NW) ? red[threadIdx.x] : 0.f;
        #pragma unroll
        for (int o = 16; o; o >>= 1) t += __shfl_xor_sync(0xffffffffu, t, o);
        if (threadIdx.x == 0) red[0] = t;
    }
    __syncthreads();
    float r = red[0];
    __syncthreads();
    return r;
}

// ------------------------- prep kernels ------------------------------------
__global__ __launch_bounds__(256) void conv_h(const float* __restrict__ h) {
    int i = blockIdx.x * 256 + threadIdx.x;      // 1,048,576 float4s
    float4 v = ((const float4*)h)[i];
    __nv_bfloat162 p0 = __floats2bfloat162_rn(v.x, v.y);
    __nv_bfloat162 p1 = __floats2bfloat162_rn(v.z, v.w);
    struct alignas(8) BF4 { __nv_bfloat162 a, b; };
    BF4 pk; pk.a = p0; pk.b = p1;
    ((BF4*)g_hb)[i] = pk;
}

__device__ __forceinline__ void transpose_body(
    const float* __restrict__ src, __nv_bfloat16* __restrict__ dst, int K, int N)
{
    __shared__ float t[32][33];
    int bn = blockIdx.x * 32, bk = blockIdx.y * 32;
    #pragma unroll
    for (int i = threadIdx.y; i < 32; i += 8)
        t[i][threadIdx.x] = src[(size_t)(bk + i) * N + bn + threadIdx.x];
    __syncthreads();
    #pragma unroll
    for (int i = threadIdx.y; i < 32; i += 8)
        dst[(size_t)(bn + i) * K + bk + threadIdx.x] =
            __float2bfloat16(t[threadIdx.x][i]);
}
__global__ void trans_wqkv(const float* __restrict__ w) { transpose_body(w, g_wqkvT, 512, 2048); }
__global__ void trans_wo (const float* __restrict__ w) { transpose_body(w, g_woT,  512, 512); }

// ------------------------- bf16 tensor-core GEMM ----------------------------
// C[M,Ntot] fp32 = A[M,512]bf16 @ B[Ntot,512]bf16^T. 128x128 tile, 8 warps as
// 2x4 (each 64x32 = 4x4 m16n8k16 atoms). K panels of 64 in smem, row stride
// 36 words (36 % 32 == 4 -> fragment LDS pattern 4g+t is conflict-free).
#define GPAD 36
__device__ __forceinline__ void gemm_body(
    const __nv_bfloat16* __restrict__ A, const __nv_bfloat16* __restrict__ B,
    float* __restrict__ C, int Ntot)
{
    extern __shared__ uint32_t sw[];
    uint32_t* As = sw;              // 128*36 = 4608 words
    uint32_t* Bs = sw + 4608;       // 4608 words
    int tid = threadIdx.x, wid = tid >> 5, lane = tid & 31;
    int wm = wid >> 2, wn = wid & 3;
    int g = lane >> 2, t = lane & 3;
    int bm = blockIdx.y * 128, bn = blockIdx.x * 128;
    const uint32_t* A32 = (const uint32_t*)A;   // 256 words per row
    const uint32_t* B32 = (const uint32_t*)B;

    float acc[4][4][4];
    #pragma unroll
    for (int i = 0; i < 4; i++)
        #pragma unroll
        for (int j = 0; j < 4; j++)
            #pragma unroll
            for (int q = 0; q < 4; q++) acc[i][j][q] = 0.f;

    for (int p = 0; p < 8; p++) {
        #pragma unroll
        for (int j = 0; j < 16; j++) {
            int i = tid + j * 256;            // 0..4095
            int r = i >> 5, c = i & 31;
            As[r * GPAD + c] = A32[(size_t)(bm + r) * 256 + p * 32 + c];
            Bs[r * GPAD + c] = B32[(size_t)(bn + r) * 256 + p * 32 + c];
        }
        __syncthreads();
        #pragma unroll
        for (int kk = 0; kk < 4; kk++) {
            uint32_t af[4][4], bf[4][2];
            #pragma unroll
            for (int i = 0; i < 4; i++) {
                int r0 = wm * 64 + i * 16;
                af[i][0] = As[(r0 + g    ) * GPAD + kk * 8 + t];
                af[i][1] = As[(r0 + g + 8) * GPAD + kk * 8 + t];
                af[i][2] = As[(r0 + g    ) * GPAD + kk * 8 + t + 4];
                af[i][3] = As[(r0 + g + 8) * GPAD + kk * 8 + t + 4];
            }
            #pragma unroll
            for (int j = 0; j < 4; j++) {
                int n0 = wn * 32 + j * 8;
                bf[j][0] = Bs[(n0 + g) * GPAD + kk * 8 + t];
                bf[j][1] = Bs[(n0 + g) * GPAD + kk * 8 + t + 4];
            }
            #pragma unroll
            for (int i = 0; i < 4; i++)
                #pragma unroll
                for (int j = 0; j < 4; j++)
                    mma16816(acc[i][j], af[i][0], af[i][1], af[i][2], af[i][3],
                             bf[j][0], bf[j][1]);
        }
        __syncthreads();
    }
    #pragma unroll
    for (int i = 0; i < 4; i++) {
        int row = bm + wm * 64 + i * 16 + g;
        #pragma unroll
        for (int j = 0; j < 4; j++) {
            int col = bn + wn * 32 + j * 8 + t * 2;
            *(float2*)&C[(size_t)row * Ntot + col] =
                make_float2(acc[i][j][0], acc[i][j][1]);
            *(float2*)&C[(size_t)(row + 8) * Ntot + col] =
                make_float2(acc[i][j][2], acc[i][j][3]);
        }
    }
}

__global__ __launch_bounds__(256) void gemm_qkv() { gemm_body(g_hb,   g_wqkvT, g_qkv, 2048); }
__global__ __launch_bounds__(256) void gemm_wo()  { gemm_body(g_ai_b, g_woT,   g_y,   512); }

// ------------------------- FAVOR+ features (fp32, emits bf16) ---------------
__global__ __launch_bounds__(256) void feat_kernel(
    const float* __restrict__ proj, const float* __restrict__ pi0,
    const float* __restrict__ pi1)
{
    extern __shared__ float sm[];
    float* proj_s = sm;              // 16384
    float* xrow   = sm + 16384;      // 256
    float* red    = sm + 16640;      // 32
    int tid = threadIdx.x;
    int lc  = blockIdx.x;
    int bh  = blockIdx.y;
    int hh  = bh & 7, b = bh >> 3;
    for (int i = tid; i < 16384; i += 256) proj_s[i] = proj[i];
    const float C = 0.3535533905932738f;   // 64^-0.25

    for (int ll = 0; ll < 64; ll++) {
        int l = lc * 64 + ll;
        __syncthreads();
        float val = g_qkv[(size_t)(l * 32 + b) * 2048 + hh * 256 + tid];
        xrow[tid] = val;
        if (tid >= 192) g_v[(size_t)(bh * 256 + l) * 64 + tid - 192] = val;
        __syncthreads();

        float xq = 0.f, x1 = 0.f, x2 = 0.f;
        #pragma unroll 8
        for (int d = 0; d < 64; d++) {
            float p = proj_s[d * 256 + tid];
            xq += xrow[d]       * p;
            x1 += xrow[64 + d]  * p;
            x2 += xrow[128 + d] * p;
        }
        xq = fminf(fmaxf(xq * C,        -30.f), 30.f);
        x1 = fminf(fmaxf(x1 * C,        -30.f), 30.f);
        x2 = fminf(fmaxf(x2 * C * 0.7f, -30.f), 30.f);

        float eqp = __expf(xq), eqm = __expf(-xq);
        float sq  = block_sum<8>(eqp + eqm, red);
        float invq = 1.f / sq;
        __nv_bfloat16* qd = g_qf_b + (size_t)(bh * 256 + l) * 512;
        qd[tid]       = __float2bfloat16(eqp * invq);
        qd[256 + tid] = __float2bfloat16(eqm * invq);

        float e1p = __expf(x1), e1m = __expf(-x1);
        float s1  = block_sum<8>(e1p + e1m, red);
        float inv1 = 1.f / s1;

        float e2p = __expf(x2), e2m = __expf(-x2);
        float s2  = block_sum<8>(e2p + e2m, red);
        float inv2 = 1.f / s2;

        float p0 = pi0[hh * 256 + l], p1v = pi1[hh * 256 + l];
        __nv_bfloat16* kd = g_kf_b + (size_t)(bh * 256 + l) * 512;
        kd[tid]       = __float2bfloat16(e1p * inv1 * p0 + e2p * inv2 * p1v);
        kd[256 + tid] = __float2bfloat16(e1m * inv1 * p0 + e2m * inv2 * p1v);
    }
}

// ------------------------- attention (mma.sync QK^T + fp32 PV) --------------
// grid (2, 256): blockIdx.x = t-chunk of 128 rows, blockIdx.y = bh.
// S[128,128] accumulated in mma fragments over 8 K-panels, masked frags
// written to smem; row-sum -> denominator; fp32 PV; output bf16.
// smem word layout: ds2[256] | Qp[4608] | Kp[4608] | Vs(8192 fl) | Ss[128*132]
#define AT_DS 0
#define AT_QP 256
#define AT_KP 4864
#define AT_VS 9472
#define AT_SS 17664
#define ATTN_SMEM ((17664 + 128 * 132) * 4)   // 138,240 B

__global__ __launch_bounds__(256) void attn3() {
    extern __shared__ uint32_t aw[];
    float* ds2 = (float*)(aw + AT_DS);
    uint32_t* Qp = aw + AT_QP;
    uint32_t* Kp = aw + AT_KP;
    float* VsF = (float*)(aw + AT_VS);
    float* SsF = (float*)(aw + AT_SS);
    int tid = threadIdx.x, wid = tid >> 5, lane = tid & 31;
    int tc = blockIdx.x, bh = blockIdx.y;
    int hh = bh & 7, b = bh >> 3;
    int ty = tid >> 4, tx = tid & 15;
    int wm = wid >> 2, wn = wid & 3;
    int g = lane >> 2, t = lane & 3;

    const uint32_t* Q32 = (const uint32_t*)g_qf_b;
    const uint32_t* K32 = (const uint32_t*)g_kf_b;
    size_t qrow0 = (size_t)bh * 256 + tc * 128;

    float dsum = 0.f;
    int drow = tid >> 1, dch = tid & 1;
    float oacc[8][4];
    #pragma unroll
    for (int i = 0; i < 8; i++)
        #pragma unroll
        for (int j = 0; j < 4; j++) oacc[i][j] = 0.f;

    for (int sc = 0; sc <= tc; sc++) {
        size_t krow0 = (size_t)bh * 256 + sc * 128;
        float acc[4][4][4];
        #pragma unroll
        for (int i = 0; i < 4; i++)
            #pragma unroll
            for (int j = 0; j < 4; j++)
                #pragma unroll
                for (int q = 0; q < 4; q++) acc[i][j][q] = 0.f;

        __syncthreads();                       // prev PV reads done
        for (int p = 0; p < 8; p++) {
            #pragma unroll
            for (int j = 0; j < 16; j++) {
                int i = tid + j * 256;
                int r = i >> 5, c = i & 31;
                Qp[r * GPAD + c] = Q32[(qrow0 + r) * 256 + p * 32 + c];
                Kp[r * GPAD + c] = K32[(krow0 + r) * 256 + p * 32 + c];
            }
            if (p == 0) {                      // V tile for this sc
                const float4* vsrc = (const float4*)(g_v + krow0 * 64);
                float4* vdst = (float4*)VsF;
                #pragma unroll
                for (int j = 0; j < 8; j++) vdst[tid + j * 256] = vsrc[tid + j * 256];
            }
            __syncthreads();
            #pragma unroll
            for (int kk = 0; kk < 4; kk++) {
                uint32_t af[4][4], bf[4][2];
                #pragma unroll
                for (int i = 0; i < 4; i++) {
                    int r0 = wm * 64 + i * 16;
                    af[i][0] = Qp[(r0 + g    ) * GPAD + kk * 8 + t];
                    af[i][1] = Qp[(r0 + g + 8) * GPAD + kk * 8 + t];
                    af[i][2] = Qp[(r0 + g    ) * GPAD + kk * 8 + t + 4];
                    af[i][3] = Qp[(r0 + g + 8) * GPAD + kk * 8 + t + 4];
                }
                #pragma unroll
                for (int j = 0; j < 4; j++) {
                    int n0 = wn * 32 + j * 8;
                    bf[j][0] = Kp[(n0 + g) * GPAD + kk * 8 + t];
                    bf[j][1] = Kp[(n0 + g) * GPAD + kk * 8 + t + 4];
                }
                #pragma unroll
                for (int i = 0; i < 4; i++)
                    #pragma unroll
                    for (int j = 0; j < 4; j++)
                        mma16816(acc[i][j], af[i][0], af[i][1], af[i][2], af[i][3],
                                 bf[j][0], bf[j][1]);
            }
            __syncthreads();
        }

        // write masked S fragments to smem
        #pragma unroll
        for (int i = 0; i < 4; i++) {
            int ra = wm * 64 + i * 16 + g, rb = ra + 8;
            #pragma unroll
            for (int j = 0; j < 4; j++) {
                int c0 = wn * 32 + j * 8 + t * 2;
                float v0 = acc[i][j][0], v1 = acc[i][j][1];
                float v2 = acc[i][j][2], v3 = acc[i][j][3];
                if (sc == tc) {
                    if (c0     > ra) v0 = 0.f;
                    if (c0 + 1 > ra) v1 = 0.f;
                    if (c0     > rb) v2 = 0.f;
                    if (c0 + 1 > rb) v3 = 0.f;
                }
                SsF[ra * 132 + c0]     = v0;
                SsF[ra * 132 + c0 + 1] = v1;
                SsF[rb * 132 + c0]     = v2;
                SsF[rb * 132 + c0 + 1] = v3;
            }
        }
        __syncthreads();                       // Ss + Vs ready

        // denominator partial: each thread sums 64 cols of its row
        {
            const float* srow = SsF + drow * 132 + dch * 64;
            float s = 0.f;
            #pragma unroll 16
            for (int q = 0; q < 64; q++) s += srow[q];
            dsum += s;
        }

        // PV: out[8 rows][4 cols] += S[128,128] @ V[128,64]
        for (int s4 = 0; s4 < 32; s4++) {
            int s0 = s4 * 4;
            float4 vv0 = *(const float4*)(VsF + (s0 + 0) * 64 + 4 * tx);
            float4 vv1 = *(const float4*)(VsF + (s0 + 1) * 64 + 4 * tx);
            float4 vv2 = *(const float4*)(VsF + (s0 + 2) * 64 + 4 * tx);
            float4 vv3 = *(const float4*)(VsF + (s0 + 3) * 64 + 4 * tx);
            #pragma unroll
            for (int i = 0; i < 8; i++) {
                float4 sv = *(const float4*)(SsF + (8 * ty + i) * 132 + s0);
                oacc[i][0] += sv.x * vv0.x + sv.y * vv1.x + sv.z * vv2.x + sv.w * vv3.x;
                oacc[i][1] += sv.x * vv0.y + sv.y * vv1.y + sv.z * vv2.y + sv.w * vv3.y;
                oacc[i][2] += sv.x * vv0.z + sv.y * vv1.z + sv.z * vv2.z + sv.w * vv3.z;
                oacc[i][3] += sv.x * vv0.w + sv.y * vv1.w + sv.z * vv2.w + sv.w * vv3.w;
            }
        }
    }

    __syncthreads();
    ds2[dch * 128 + drow] = dsum;
    __syncthreads();
    #pragma unroll
    for (int i = 0; i < 8; i++) {
        int r = 8 * ty + i;
        float den = ds2[r] + ds2[128 + r] + 1e-5f;
        float inv = 0.125f / den;
        int l = tc * 128 + r;
        __nv_bfloat16* dst = g_ai_b + (size_t)(l * 32 + b) * 512 + hh * 64 + 4 * tx;
        *(__nv_bfloat162*)(dst)     = __floats2bfloat162_rn(oacc[i][0] * inv, oacc[i][1] * inv);
        *(__nv_bfloat162*)(dst + 2) = __floats2bfloat162_rn(oacc[i][2] * inv, oacc[i][3] * inv);
    }
}

// ------------------------- residual + LayerNorm ----------------------------
__global__ __launch_bounds__(512) void ln_kernel(
    const float* __restrict__ hin, const float* __restrict__ gamma,
    const float* __restrict__ beta, float* __restrict__ out)
{
    __shared__ float red[32];
    int r = blockIdx.x, j = threadIdx.x;
    float x = g_y[(size_t)r * 512 + j] + hin[(size_t)r * 512 + j];
    float s1 = block_sum<16>(x, red);
    float mu = s1 * (1.f / 512.f);
    float d = x - mu;
    float s2 = block_sum<16>(d * d, red);
    float rstd = rsqrtf(s2 * (1.f / 512.f) + 1e-5f);
    out[(size_t)r * 512 + j] = d * rstd * gamma[j] + beta[j];
}

// ------------------------- launch ------------------------------------------
extern "C" void kernel_launch(void* const* d_in, const int* in_sizes, int n_in,
                              void* d_out, int out_size) {
    const float* h     = (const float*)d_in[0];
    const float* wqkv  = (const float*)d_in[1];
    const float* wo    = (const float*)d_in[2];
    const float* gamma = (const float*)d_in[3];
    const float* beta  = (const float*)d_in[4];
    const float* pi0   = (const float*)d_in[5];
    const float* pi1   = (const float*)d_in[6];
    const float* proj  = (const float*)d_in[7];

    const int FEAT_SMEM = (16384 + 256 + 32) * 4;   // 66,688 B
    const int GEMM_SMEM = 2 * 4608 * 4;             // 36,864 B
    cudaFuncSetAttribute(feat_kernel, cudaFuncAttributeMaxDynamicSharedMemorySize, FEAT_SMEM);
    cudaFuncSetAttribute(attn3,       cudaFuncAttributeMaxDynamicSharedMemorySize, ATTN_SMEM);

    conv_h<<<4096, 256>>>(h);
    trans_wqkv<<<dim3(64, 16), dim3(32, 8)>>>(wqkv);
    trans_wo  <<<dim3(16, 16), dim3(32, 8)>>>(wo);
    gemm_qkv<<<dim3(16, 64), 256, GEMM_SMEM>>>();
    feat_kernel<<<dim3(4, 256), 256, FEAT_SMEM>>>(proj, pi0, pi1);
    attn3<<<dim3(2, 256), 256, ATTN_SMEM>>>();
    gemm_wo<<<dim3(4, 64), 256, GEMM_SMEM>>>();
    ln_kernel<<<8192, 512>>>(h, gamma, beta, (float*)d_out);
}

// round 8
// speedup vs baseline: 1.7023x; 1.0079x over previous
#include <cuda_runtime.h>
#include <cuda_bf16.h>
#include <cstdint>

// ---------------------------------------------------------------------------
// L=256, B=32, D_MODEL=512, N_HEAD=8, D_HEAD=64, 2m=512
// Tensor path via baseline mma.sync (m16n8k16 bf16) — tcgen05 is 'a'-feature
// gated and the harness builds for plain sm_103.
// Device globals only bound inside device code (GB300/ATS pitfall).
// ---------------------------------------------------------------------------
#define ROWS 8192
#define BH 256

__device__ float          g_qkv[ROWS * 2048];        // fp32 qkv output
__device__ __nv_bfloat16  g_hb [ROWS * 512];         // h in bf16
__device__ __nv_bfloat16  g_wqkvT[2048 * 512];       // wqkv^T bf16 [N,K]
__device__ __nv_bfloat16  g_woT [512 * 512];         // wo^T bf16 [N,K]
__device__ __nv_bfloat16  g_qf_b[BH * 256 * 512];    // features bf16
__device__ __nv_bfloat16  g_kf_b[BH * 256 * 512];
__device__ float          g_v  [BH * 256 * 64];
__device__ __nv_bfloat16  g_ai_b[ROWS * 512];        // attn out bf16 [l*32+b,512]
__device__ float          g_y  [ROWS * 512];

// ------------------------- mma.sync helper ----------------------------------
__device__ __forceinline__ void mma16816(float c[4],
    uint32_t a0, uint32_t a1, uint32_t a2, uint32_t a3,
    uint32_t b0, uint32_t b1)
{
    asm volatile(
        "mma.sync.aligned.m16n8k16.row.col.f32.bf16.bf16.f32 "
        "{%0,%1,%2,%3}, {%4,%5,%6,%7}, {%8,%9}, {%0,%1,%2,%3};"
        : "+f"(c[0]), "+f"(c[1]), "+f"(c[2]), "+f"(c[3])
        : "r"(a0), "r"(a1), "r"(a2), "r"(a3), "r"(b0), "r"(b1));
}

// ------------------------- block sum reduction ------------------------------
template<int NW>
__device__ __forceinline__ float block_sum(float v, float* red) {
    #pragma unroll
    for (int o = 16; o; o >>= 1) v += __shfl_xor_sync(0xffffffffu, v, o);
    if ((threadIdx.x & 31) == 0) red[threadIdx.x >> 5] = v;
    __syncthreads();
    if (threadIdx.x < 32) {
        float t = (threadIdx.x < NW) ? red[threadIdx.x] : 0.f;
        #pragma unroll
        for (int o = 16; o; o >>= 1) t += __shfl_xor_sync(0xffffffffu, t, o);
        if (threadIdx.x == 0) red[0] = t;
    }
    __syncthreads();
    float r = red[0];
    __syncthreads();
    return r;
}

// ------------------------- prep kernels ------------------------------------
__global__ __launch_bounds__(256) void conv_h(const float* __restrict__ h) {
    int i = blockIdx.x * 256 + threadIdx.x;      // 1,048,576 float4s
    float4 v = ((const float4*)h)[i];
    __nv_bfloat162 p0 = __floats2bfloat162_rn(v.x, v.y);
    __nv_bfloat162 p1 = __floats2bfloat162_rn(v.z, v.w);
    struct alignas(8) BF4 { __nv_bfloat162 a, b; };
    BF4 pk; pk.a = p0; pk.b = p1;
    ((BF4*)g_hb)[i] = pk;
}

__device__ __forceinline__ void transpose_body(
    const float* __restrict__ src, __nv_bfloat16* __restrict__ dst, int K, int N)
{
    __shared__ float t[32][33];
    int bn = blockIdx.x * 32, bk = blockIdx.y * 32;
    #pragma unroll
    for (int i = threadIdx.y; i < 32; i += 8)
        t[i][threadIdx.x] = src[(size_t)(bk + i) * N + bn + threadIdx.x];
    __syncthreads();
    #pragma unroll
    for (int i = threadIdx.y; i < 32; i += 8)
        dst[(size_t)(bn + i) * K + bk + threadIdx.x] =
            __float2bfloat16(t[threadIdx.x][i]);
}
__global__ void trans_wqkv(const float* __restrict__ w) { transpose_body(w, g_wqkvT, 512, 2048); }
__global__ void trans_wo (const float* __restrict__ w) { transpose_body(w, g_woT,  512, 512); }

// ------------------------- bf16 tensor-core GEMM ----------------------------
// C[M,Ntot] fp32 = A[M,512]bf16 @ B[Ntot,512]bf16^T. 128x128 tile, 8 warps as
// 2x4 (each 64x32 = 4x4 m16n8k16 atoms). K panels of 64 in smem, row stride
// 36 words (36 % 32 == 4 -> fragment LDS pattern 4g+t is conflict-free).
#define GPAD 36
__device__ __forceinline__ void gemm_body(
    const __nv_bfloat16* __restrict__ A, const __nv_bfloat16* __restrict__ B,
    float* __restrict__ C, int Ntot)
{
    extern __shared__ uint32_t sw[];
    uint32_t* As = sw;              // 128*36 = 4608 words
    uint32_t* Bs = sw + 4608;       // 4608 words
    int tid = threadIdx.x, wid = tid >> 5, lane = tid & 31;
    int wm = wid >> 2, wn = wid & 3;
    int g = lane >> 2, t = lane & 3;
    int bm = blockIdx.y * 128, bn = blockIdx.x * 128;
    const uint32_t* A32 = (const uint32_t*)A;   // 256 words per row
    const uint32_t* B32 = (const uint32_t*)B;

    float acc[4][4][4];
    #pragma unroll
    for (int i = 0; i < 4; i++)
        #pragma unroll
        for (int j = 0; j < 4; j++)
            #pragma unroll
            for (int q = 0; q < 4; q++) acc[i][j][q] = 0.f;

    for (int p = 0; p < 8; p++) {
        #pragma unroll
        for (int j = 0; j < 16; j++) {
            int i = tid + j * 256;            // 0..4095
            int r = i >> 5, c = i & 31;
            As[r * GPAD + c] = A32[(size_t)(bm + r) * 256 + p * 32 + c];
            Bs[r * GPAD + c] = B32[(size_t)(bn + r) * 256 + p * 32 + c];
        }
        __syncthreads();
        #pragma unroll
        for (int kk = 0; kk < 4; kk++) {
            uint32_t af[4][4], bf[4][2];
            #pragma unroll
            for (int i = 0; i < 4; i++) {
                int r0 = wm * 64 + i * 16;
                af[i][0] = As[(r0 + g    ) * GPAD + kk * 8 + t];
                af[i][1] = As[(r0 + g + 8) * GPAD + kk * 8 + t];
                af[i][2] = As[(r0 + g    ) * GPAD + kk * 8 + t + 4];
                af[i][3] = As[(r0 + g + 8) * GPAD + kk * 8 + t + 4];
            }
            #pragma unroll
            for (int j = 0; j < 4; j++) {
                int n0 = wn * 32 + j * 8;
                bf[j][0] = Bs[(n0 + g) * GPAD + kk * 8 + t];
                bf[j][1] = Bs[(n0 + g) * GPAD + kk * 8 + t + 4];
            }
            #pragma unroll
            for (int i = 0; i < 4; i++)
                #pragma unroll
                for (int j = 0; j < 4; j++)
                    mma16816(acc[i][j], af[i][0], af[i][1], af[i][2], af[i][3],
                             bf[j][0], bf[j][1]);
        }
        __syncthreads();
    }
    #pragma unroll
    for (int i = 0; i < 4; i++) {
        int row = bm + wm * 64 + i * 16 + g;
        #pragma unroll
        for (int j = 0; j < 4; j++) {
            int col = bn + wn * 32 + j * 8 + t * 2;
            *(float2*)&C[(size_t)row * Ntot + col] =
                make_float2(acc[i][j][0], acc[i][j][1]);
            *(float2*)&C[(size_t)(row + 8) * Ntot + col] =
                make_float2(acc[i][j][2], acc[i][j][3]);
        }
    }
}

__global__ __launch_bounds__(256) void gemm_qkv() { gemm_body(g_hb,   g_wqkvT, g_qkv, 2048); }
__global__ __launch_bounds__(256) void gemm_wo()  { gemm_body(g_ai_b, g_woT,   g_y,   512); }

// ------------------------- FAVOR+ features (fp32, emits bf16) ---------------
__global__ __launch_bounds__(256) void feat_kernel(
    const float* __restrict__ proj, const float* __restrict__ pi0,
    const float* __restrict__ pi1)
{
    extern __shared__ float sm[];
    float* proj_s = sm;              // 16384
    float* xrow   = sm + 16384;      // 256
    float* red    = sm + 16640;      // 32
    int tid = threadIdx.x;
    int lc  = blockIdx.x;
    int bh  = blockIdx.y;
    int hh  = bh & 7, b = bh >> 3;
    for (int i = tid; i < 16384; i += 256) proj_s[i] = proj[i];
    const float C = 0.3535533905932738f;   // 64^-0.25

    for (int ll = 0; ll < 64; ll++) {
        int l = lc * 64 + ll;
        __syncthreads();
        float val = g_qkv[(size_t)(l * 32 + b) * 2048 + hh * 256 + tid];
        xrow[tid] = val;
        if (tid >= 192) g_v[(size_t)(bh * 256 + l) * 64 + tid - 192] = val;
        __syncthreads();

        float xq = 0.f, x1 = 0.f, x2 = 0.f;
        #pragma unroll 8
        for (int d = 0; d < 64; d++) {
            float p = proj_s[d * 256 + tid];
            xq += xrow[d]       * p;
            x1 += xrow[64 + d]  * p;
            x2 += xrow[128 + d] * p;
        }
        xq = fminf(fmaxf(xq * C,        -30.f), 30.f);
        x1 = fminf(fmaxf(x1 * C,        -30.f), 30.f);
        x2 = fminf(fmaxf(x2 * C * 0.7f, -30.f), 30.f);

        float eqp = __expf(xq), eqm = __expf(-xq);
        float sq  = block_sum<8>(eqp + eqm, red);
        float invq = 1.f / sq;
        __nv_bfloat16* qd = g_qf_b + (size_t)(bh * 256 + l) * 512;
        qd[tid]       = __float2bfloat16(eqp * invq);
        qd[256 + tid] = __float2bfloat16(eqm * invq);

        float e1p = __expf(x1), e1m = __expf(-x1);
        float s1  = block_sum<8>(e1p + e1m, red);
        float inv1 = 1.f / s1;

        float e2p = __expf(x2), e2m = __expf(-x2);
        float s2  = block_sum<8>(e2p + e2m, red);
        float inv2 = 1.f / s2;

        float p0 = pi0[hh * 256 + l], p1v = pi1[hh * 256 + l];
        __nv_bfloat16* kd = g_kf_b + (size_t)(bh * 256 + l) * 512;
        kd[tid]       = __float2bfloat16(e1p * inv1 * p0 + e2p * inv2 * p1v);
        kd[256 + tid] = __float2bfloat16(e1m * inv1 * p0 + e2m * inv2 * p1v);
    }
}

// ------------------------- attention (mma.sync QK^T + fp32 PV) --------------
// grid (2, 256): blockIdx.x = t-chunk of 128 rows, blockIdx.y = bh.
// S[128,128] accumulated in mma fragments over 8 K-panels, masked frags
// written to smem; row-sum -> denominator; fp32 PV; output bf16.
// smem word layout: ds2[256] | Qp[4608] | Kp[4608] | Vs(8192 fl) | Ss[128*132]
#define AT_DS 0
#define AT_QP 256
#define AT_KP 4864
#define AT_VS 9472
#define AT_SS 17664
#define ATTN_SMEM ((17664 + 128 * 132) * 4)   // 138,240 B

__global__ __launch_bounds__(256) void attn3() {
    extern __shared__ uint32_t aw[];
    float* ds2 = (float*)(aw + AT_DS);
    uint32_t* Qp = aw + AT_QP;
    uint32_t* Kp = aw + AT_KP;
    float* VsF = (float*)(aw + AT_VS);
    float* SsF = (float*)(aw + AT_SS);
    int tid = threadIdx.x, wid = tid >> 5, lane = tid & 31;
    int tc = blockIdx.x, bh = blockIdx.y;
    int hh = bh & 7, b = bh >> 3;
    int ty = tid >> 4, tx = tid & 15;
    int wm = wid >> 2, wn = wid & 3;
    int g = lane >> 2, t = lane & 3;

    const uint32_t* Q32 = (const uint32_t*)g_qf_b;
    const uint32_t* K32 = (const uint32_t*)g_kf_b;
    size_t qrow0 = (size_t)bh * 256 + tc * 128;

    float dsum = 0.f;
    int drow = tid >> 1, dch = tid & 1;
    float oacc[8][4];
    #pragma unroll
    for (int i = 0; i < 8; i++)
        #pragma unroll
        for (int j = 0; j < 4; j++) oacc[i][j] = 0.f;

    for (int sc = 0; sc <= tc; sc++) {
        size_t krow0 = (size_t)bh * 256 + sc * 128;
        float acc[4][4][4];
        #pragma unroll
        for (int i = 0; i < 4; i++)
            #pragma unroll
            for (int j = 0; j < 4; j++)
                #pragma unroll
                for (int q = 0; q < 4; q++) acc[i][j][q] = 0.f;

        __syncthreads();                       // prev PV reads done
        for (int p = 0; p < 8; p++) {
            #pragma unroll
            for (int j = 0; j < 16; j++) {
                int i = tid + j * 256;
                int r = i >> 5, c = i & 31;
                Qp[r * GPAD + c] = Q32[(qrow0 + r) * 256 + p * 32 + c];
                Kp[r * GPAD + c] = K32[(krow0 + r) * 256 + p * 32 + c];
            }
            if (p == 0) {                      // V tile for this sc
                const float4* vsrc = (const float4*)(g_v + krow0 * 64);
                float4* vdst = (float4*)VsF;
                #pragma unroll
                for (int j = 0; j < 8; j++) vdst[tid + j * 256] = vsrc[tid + j * 256];
            }
            __syncthreads();
            #pragma unroll
            for (int kk = 0; kk < 4; kk++) {
                uint32_t af[4][4], bf[4][2];
                #pragma unroll
                for (int i = 0; i < 4; i++) {
                    int r0 = wm * 64 + i * 16;
                    af[i][0] = Qp[(r0 + g    ) * GPAD + kk * 8 + t];
                    af[i][1] = Qp[(r0 + g + 8) * GPAD + kk * 8 + t];
                    af[i][2] = Qp[(r0 + g    ) * GPAD + kk * 8 + t + 4];
                    af[i][3] = Qp[(r0 + g + 8) * GPAD + kk * 8 + t + 4];
                }
                #pragma unroll
                for (int j = 0; j < 4; j++) {
                    int n0 = wn * 32 + j * 8;
                    bf[j][0] = Kp[(n0 + g) * GPAD + kk * 8 + t];
                    bf[j][1] = Kp[(n0 + g) * GPAD + kk * 8 + t + 4];
                }
                #pragma unroll
                for (int i = 0; i < 4; i++)
                    #pragma unroll
                    for (int j = 0; j < 4; j++)
                        mma16816(acc[i][j], af[i][0], af[i][1], af[i][2], af[i][3],
                                 bf[j][0], bf[j][1]);
            }
            __syncthreads();
        }

        // write masked S fragments to smem
        #pragma unroll
        for (int i = 0; i < 4; i++) {
            int ra = wm * 64 + i * 16 + g, rb = ra + 8;
            #pragma unroll
            for (int j = 0; j < 4; j++) {
                int c0 = wn * 32 + j * 8 + t * 2;
                float v0 = acc[i][j][0], v1 = acc[i][j][1];
                float v2 = acc[i][j][2], v3 = acc[i][j][3];
                if (sc == tc) {
                    if (c0     > ra) v0 = 0.f;
                    if (c0 + 1 > ra) v1 = 0.f;
                    if (c0     > rb) v2 = 0.f;
                    if (c0 + 1 > rb) v3 = 0.f;
                }
                SsF[ra * 132 + c0]     = v0;
                SsF[ra * 132 + c0 + 1] = v1;
                SsF[rb * 132 + c0]     = v2;
                SsF[rb * 132 + c0 + 1] = v3;
            }
        }
        __syncthreads();                       // Ss + Vs ready

        // denominator partial: each thread sums 64 cols of its row
        {
            const float* srow = SsF + drow * 132 + dch * 64;
            float s = 0.f;
            #pragma unroll 16
            for (int q = 0; q < 64; q++) s += srow[q];
            dsum += s;
        }

        // PV: out[8 rows][4 cols] += S[128,128] @ V[128,64]
        for (int s4 = 0; s4 < 32; s4++) {
            int s0 = s4 * 4;
            float4 vv0 = *(const float4*)(VsF + (s0 + 0) * 64 + 4 * tx);
            float4 vv1 = *(const float4*)(VsF + (s0 + 1) * 64 + 4 * tx);
            float4 vv2 = *(const float4*)(VsF + (s0 + 2) * 64 + 4 * tx);
            float4 vv3 = *(const float4*)(VsF + (s0 + 3) * 64 + 4 * tx);
            #pragma unroll
            for (int i = 0; i < 8; i++) {
                float4 sv = *(const float4*)(SsF + (8 * ty + i) * 132 + s0);
                oacc[i][0] += sv.x * vv0.x + sv.y * vv1.x + sv.z * vv2.x + sv.w * vv3.x;
                oacc[i][1] += sv.x * vv0.y + sv.y * vv1.y + sv.z * vv2.y + sv.w * vv3.y;
                oacc[i][2] += sv.x * vv0.z + sv.y * vv1.z + sv.z * vv2.z + sv.w * vv3.z;
                oacc[i][3] += sv.x * vv0.w + sv.y * vv1.w + sv.z * vv2.w + sv.w * vv3.w;
            }
        }
    }

    __syncthreads();
    ds2[dch * 128 + drow] = dsum;
    __syncthreads();
    #pragma unroll
    for (int i = 0; i < 8; i++) {
        int r = 8 * ty + i;
        float den = ds2[r] + ds2[128 + r] + 1e-5f;
        float inv = 0.125f / den;
        int l = tc * 128 + r;
        __nv_bfloat16* dst = g_ai_b + (size_t)(l * 32 + b) * 512 + hh * 64 + 4 * tx;
        *(__nv_bfloat162*)(dst)     = __floats2bfloat162_rn(oacc[i][0] * inv, oacc[i][1] * inv);
        *(__nv_bfloat162*)(dst + 2) = __floats2bfloat162_rn(oacc[i][2] * inv, oacc[i][3] * inv);
    }
}

// ------------------------- residual + LayerNorm ----------------------------
__global__ __launch_bounds__(512) void ln_kernel(
    const float* __restrict__ hin, const float* __restrict__ gamma,
    const float* __restrict__ beta, float* __restrict__ out)
{
    __shared__ float red[32];
    int r = blockIdx.x, j = threadIdx.x;
    float x = g_y[(size_t)r * 512 + j] + hin[(size_t)r * 512 + j];
    float s1 = block_sum<16>(x, red);
    float mu = s1 * (1.f / 512.f);
    float d = x - mu;
    float s2 = block_sum<16>(d * d, red);
    float rstd = rsqrtf(s2 * (1.f / 512.f) + 1e-5f);
    out[(size_t)r * 512 + j] = d * rstd * gamma[j] + beta[j];
}

// ------------------------- launch ------------------------------------------
extern "C" void kernel_launch(void* const* d_in, const int* in_sizes, int n_in,
                              void* d_out, int out_size) {
    const float* h     = (const float*)d_in[0];
    const float* wqkv  = (const float*)d_in[1];
    const float* wo    = (const float*)d_in[2];
    const float* gamma = (const float*)d_in[3];
    const float* beta  = (const float*)d_in[4];
    const float* pi0   = (const float*)d_in[5];
    const float* pi1   = (const float*)d_in[6];
    const float* proj  = (const float*)d_in[7];

    const int FEAT_SMEM = (16384 + 256 + 32) * 4;   // 66,688 B
    const int GEMM_SMEM = 2 * 4608 * 4;             // 36,864 B
    cudaFuncSetAttribute(feat_kernel, cudaFuncAttributeMaxDynamicSharedMemorySize, FEAT_SMEM);
    cudaFuncSetAttribute(attn3,       cudaFuncAttributeMaxDynamicSharedMemorySize, ATTN_SMEM);

    conv_h<<<4096, 256>>>(h);
    trans_wqkv<<<dim3(64, 16), dim3(32, 8)>>>(wqkv);
    trans_wo  <<<dim3(16, 16), dim3(32, 8)>>>(wo);
    gemm_qkv<<<dim3(16, 64), 256, GEMM_SMEM>>>();
    feat_kernel<<<dim3(4, 256), 256, FEAT_SMEM>>>(proj, pi0, pi1);
    attn3<<<dim3(2, 256), 256, ATTN_SMEM>>>();
    gemm_wo<<<dim3(4, 64), 256, GEMM_SMEM>>>();
    ln_kernel<<<8192, 512>>>(h, gamma, beta, (float*)d_out);
}

// round 9
// speedup vs baseline: 3.9864x; 2.3419x over previous
#include <cuda_runtime.h>
#include <cuda_bf16.h>
#include <cstdint>

// ---------------------------------------------------------------------------
// L=256, B=32, D_MODEL=512, N_HEAD=8, D_HEAD=64, 2m=512
// All GEMM-shaped work on mma.sync m16n8k16 bf16 (tcgen05 is 'a'-gated):
//   qkv GEMM, FAVOR+ projection (feat2), S=qf@kf^T AND PV (attn4), wo GEMM.
// Device globals only bound inside device code (GB300/ATS pitfall).
// ---------------------------------------------------------------------------
#define ROWS 8192
#define BH 256

__device__ float          g_qkv[ROWS * 2048];        // fp32 qkv output
__device__ __nv_bfloat16  g_hb [ROWS * 512];         // h in bf16
__device__ __nv_bfloat16  g_wqkvT[2048 * 512];       // wqkv^T bf16 [N,K]
__device__ __nv_bfloat16  g_woT [512 * 512];         // wo^T bf16 [N,K]
__device__ __nv_bfloat16  g_pT  [256 * 64];          // (C*proj)^T bf16 [m][d]
__device__ __nv_bfloat16  g_qf_b[BH * 256 * 512];    // features bf16
__device__ __nv_bfloat16  g_kf_b[BH * 256 * 512];
__device__ __nv_bfloat16  g_vt [BH * 64 * 256];      // V^T bf16 [bh*64+d][l]
__device__ __nv_bfloat16  g_ai_b[ROWS * 512];        // attn out bf16
__device__ float          g_y  [ROWS * 512];

// ------------------------- helpers ------------------------------------------
__device__ __forceinline__ void mma16816(float c[4],
    uint32_t a0, uint32_t a1, uint32_t a2, uint32_t a3,
    uint32_t b0, uint32_t b1)
{
    asm volatile(
        "mma.sync.aligned.m16n8k16.row.col.f32.bf16.bf16.f32 "
        "{%0,%1,%2,%3}, {%4,%5,%6,%7}, {%8,%9}, {%0,%1,%2,%3};"
        : "+f"(c[0]), "+f"(c[1]), "+f"(c[2]), "+f"(c[3])
        : "r"(a0), "r"(a1), "r"(a2), "r"(a3), "r"(b0), "r"(b1));
}
__device__ __forceinline__ uint32_t pk2(float a, float b) {
    __nv_bfloat162 t = __floats2bfloat162_rn(a, b);
    return *(uint32_t*)&t;
}
__device__ __forceinline__ uint32_t addbf2(uint32_t x, uint32_t y) {
    __nv_bfloat162 a = *(__nv_bfloat162*)&x, b = *(__nv_bfloat162*)&y;
    __nv_bfloat162 r = __hadd2(a, b);
    return *(uint32_t*)&r;
}

template<int NW>
__device__ __forceinline__ float block_sum(float v, float* red) {
    #pragma unroll
    for (int o = 16; o; o >>= 1) v += __shfl_xor_sync(0xffffffffu, v, o);
    if ((threadIdx.x & 31) == 0) red[threadIdx.x >> 5] = v;
    __syncthreads();
    if (threadIdx.x < 32) {
        float t = (threadIdx.x < NW) ? red[threadIdx.x] : 0.f;
        #pragma unroll
        for (int o = 16; o; o >>= 1) t += __shfl_xor_sync(0xffffffffu, t, o);
        if (threadIdx.x == 0) red[0] = t;
    }
    __syncthreads();
    float r = red[0];
    __syncthreads();
    return r;
}

// ------------------------- prep kernels ------------------------------------
__global__ __launch_bounds__(256) void conv_h(const float* __restrict__ h) {
    int i = blockIdx.x * 256 + threadIdx.x;
    float4 v = ((const float4*)h)[i];
    struct alignas(8) BF4 { __nv_bfloat162 a, b; };
    BF4 pk;
    pk.a = __floats2bfloat162_rn(v.x, v.y);
    pk.b = __floats2bfloat162_rn(v.z, v.w);
    ((BF4*)g_hb)[i] = pk;
}

__device__ __forceinline__ void transpose_body(
    const float* __restrict__ src, __nv_bfloat16* __restrict__ dst, int K, int N)
{
    __shared__ float t[32][33];
    int bn = blockIdx.x * 32, bk = blockIdx.y * 32;
    #pragma unroll
    for (int i = threadIdx.y; i < 32; i += 8)
        t[i][threadIdx.x] = src[(size_t)(bk + i) * N + bn + threadIdx.x];
    __syncthreads();
    #pragma unroll
    for (int i = threadIdx.y; i < 32; i += 8)
        dst[(size_t)(bn + i) * K + bk + threadIdx.x] =
            __float2bfloat16(t[threadIdx.x][i]);
}
__global__ void trans_wqkv(const float* __restrict__ w) { transpose_body(w, g_wqkvT, 512, 2048); }
__global__ void trans_wo (const float* __restrict__ w) { transpose_body(w, g_woT,  512, 512); }

// (C*proj)^T: g_pT[m][d] = bf16(C * proj[d][m]),  C = 64^-0.25
__global__ __launch_bounds__(256) void prep_pT(const float* __restrict__ proj) {
    int i = blockIdx.x * 256 + threadIdx.x;      // 16384
    int d = i >> 8, m = i & 255;
    g_pT[m * 64 + d] = __float2bfloat16(proj[i] * 0.3535533905932738f);
}

// ------------------------- bf16 tensor-core GEMM ----------------------------
#define GPAD 36
__device__ __forceinline__ void gemm_body(
    const __nv_bfloat16* __restrict__ A, const __nv_bfloat16* __restrict__ B,
    float* __restrict__ C, int Ntot)
{
    extern __shared__ uint32_t sw[];
    uint32_t* As = sw;              // 128*36
    uint32_t* Bs = sw + 4608;
    int tid = threadIdx.x, wid = tid >> 5, lane = tid & 31;
    int wm = wid >> 2, wn = wid & 3;
    int g = lane >> 2, t = lane & 3;
    int bm = blockIdx.y * 128, bn = blockIdx.x * 128;
    const uint32_t* A32 = (const uint32_t*)A;
    const uint32_t* B32 = (const uint32_t*)B;

    float acc[4][4][4];
    #pragma unroll
    for (int i = 0; i < 4; i++)
        #pragma unroll
        for (int j = 0; j < 4; j++)
            #pragma unroll
            for (int q = 0; q < 4; q++) acc[i][j][q] = 0.f;

    for (int p = 0; p < 8; p++) {
        #pragma unroll
        for (int j = 0; j < 16; j++) {
            int i = tid + j * 256;
            int r = i >> 5, c = i & 31;
            As[r * GPAD + c] = A32[(size_t)(bm + r) * 256 + p * 32 + c];
            Bs[r * GPAD + c] = B32[(size_t)(bn + r) * 256 + p * 32 + c];
        }
        __syncthreads();
        #pragma unroll
        for (int kk = 0; kk < 4; kk++) {
            uint32_t af[4][4], bf[4][2];
            #pragma unroll
            for (int i = 0; i < 4; i++) {
                int r0 = wm * 64 + i * 16;
                af[i][0] = As[(r0 + g    ) * GPAD + kk * 8 + t];
                af[i][1] = As[(r0 + g + 8) * GPAD + kk * 8 + t];
                af[i][2] = As[(r0 + g    ) * GPAD + kk * 8 + t + 4];
                af[i][3] = As[(r0 + g + 8) * GPAD + kk * 8 + t + 4];
            }
            #pragma unroll
            for (int j = 0; j < 4; j++) {
                int n0 = wn * 32 + j * 8;
                bf[j][0] = Bs[(n0 + g) * GPAD + kk * 8 + t];
                bf[j][1] = Bs[(n0 + g) * GPAD + kk * 8 + t + 4];
            }
            #pragma unroll
            for (int i = 0; i < 4; i++)
                #pragma unroll
                for (int j = 0; j < 4; j++)
                    mma16816(acc[i][j], af[i][0], af[i][1], af[i][2], af[i][3],
                             bf[j][0], bf[j][1]);
        }
        __syncthreads();
    }
    #pragma unroll
    for (int i = 0; i < 4; i++) {
        int row = bm + wm * 64 + i * 16 + g;
        #pragma unroll
        for (int j = 0; j < 4; j++) {
            int col = bn + wn * 32 + j * 8 + t * 2;
            *(float2*)&C[(size_t)row * Ntot + col] =
                make_float2(acc[i][j][0], acc[i][j][1]);
            *(float2*)&C[(size_t)(row + 8) * Ntot + col] =
                make_float2(acc[i][j][2], acc[i][j][3]);
        }
    }
}
__global__ __launch_bounds__(256) void gemm_qkv() { gemm_body(g_hb,   g_wqkvT, g_qkv, 2048); }
__global__ __launch_bounds__(256) void gemm_wo()  { gemm_body(g_ai_b, g_woT,   g_y,   512); }

// ------------------------- feat2: FAVOR+ via tensor cores -------------------
// grid (4, 256): blockIdx.x = 64-row tile, blockIdx.y = bh. 8 warps as 2x4.
// Per seg (q,k1,0.7*k2): [64,64]@[64,256] mma, exp epilogue from fragments,
// row-sums via quad-shfl + smem, packed coalesced writes via staging tile.
// Also emits V^T bf16. Word map: P[9216] | X[3*2304] | V[2304] | STG[8448] | SS[256]
#define F_P 0
#define F_X 9216
#define F_V 16128
#define F_STG 18432
#define F_SS 26880
#define FEAT2_SMEM (27136 * 4)     // 108,544 B

__global__ __launch_bounds__(256) void feat2(
    const float* __restrict__ pi0, const float* __restrict__ pi1)
{
    extern __shared__ uint32_t fw[];
    __nv_bfloat16* Xh = (__nv_bfloat16*)(fw + F_X);   // seg*4608 + r*72 + d
    __nv_bfloat16* Vh = (__nv_bfloat16*)(fw + F_V);   // l*72 + d
    float* ss = (float*)(fw + F_SS);
    int tid = threadIdx.x, wid = tid >> 5, lane = tid & 31;
    int wm = wid >> 2, wn = wid & 3;
    int g = lane >> 2, t = lane & 3;
    int l0 = blockIdx.x * 64, bh = blockIdx.y;
    int hh = bh & 7, b = bh >> 3;

    // load P^T (8192 words)
    const uint32_t* pTw = (const uint32_t*)g_pT;
    #pragma unroll
    for (int w = 0; w < 32; w++) {
        int idx = tid + w * 256;
        int m = idx >> 5, wd = idx & 31;
        fw[F_P + m * 36 + wd] = pTw[m * 32 + wd];
    }
    // load X (q,k1,0.7*k2) + V from fp32 qkv
    #pragma unroll
    for (int w = 0; w < 64; w++) {
        int idx = tid + w * 256;
        int r = idx >> 8, c = idx & 255;
        float v = g_qkv[(size_t)((l0 + r) * 32 + b) * 2048 + hh * 256 + c];
        if (c < 192) {
            int seg = c >> 6, d = c & 63;
            if (seg == 2) v *= 0.7f;
            Xh[seg * 4608 + r * 72 + d] = __float2bfloat16(v);
        } else {
            Vh[r * 72 + (c - 192)] = __float2bfloat16(v);
        }
    }
    __syncthreads();

    // V^T -> global: g_vt[bh*64+d][l0+l]
    #pragma unroll
    for (int w = 0; w < 16; w++) {
        int idx = tid + w * 256;
        int d = idx >> 6, l = idx & 63;
        g_vt[(size_t)(bh * 64 + d) * 256 + l0 + l] = Vh[l * 72 + d];
    }

    for (int seg = 0; seg < 3; seg++) {
        const int XB = F_X + seg * 2304;
        float acc[2][8][4];
        #pragma unroll
        for (int i = 0; i < 2; i++)
            #pragma unroll
            for (int j = 0; j < 8; j++)
                #pragma unroll
                for (int q = 0; q < 4; q++) acc[i][j][q] = 0.f;

        #pragma unroll
        for (int kk = 0; kk < 4; kk++) {
            uint32_t af[2][4], bf[8][2];
            #pragma unroll
            for (int i = 0; i < 2; i++) {
                int r0 = wm * 32 + i * 16;
                af[i][0] = fw[XB + (r0 + g    ) * 36 + kk * 8 + t];
                af[i][1] = fw[XB + (r0 + g + 8) * 36 + kk * 8 + t];
                af[i][2] = fw[XB + (r0 + g    ) * 36 + kk * 8 + t + 4];
                af[i][3] = fw[XB + (r0 + g + 8) * 36 + kk * 8 + t + 4];
            }
            #pragma unroll
            for (int j = 0; j < 8; j++) {
                int n0 = wn * 64 + j * 8;
                bf[j][0] = fw[F_P + (n0 + g) * 36 + kk * 8 + t];
                bf[j][1] = fw[F_P + (n0 + g) * 36 + kk * 8 + t + 4];
            }
            #pragma unroll
            for (int i = 0; i < 2; i++)
                #pragma unroll
                for (int j = 0; j < 8; j++)
                    mma16816(acc[i][j], af[i][0], af[i][1], af[i][2], af[i][3],
                             bf[j][0], bf[j][1]);
        }

        // exp in place + row partial sums of (e + 1/e)
        float pr[2][2] = {{0.f, 0.f}, {0.f, 0.f}};
        #pragma unroll
        for (int i = 0; i < 2; i++)
            #pragma unroll
            for (int j = 0; j < 8; j++)
                #pragma unroll
                for (int q = 0; q < 4; q++) {
                    float v = fminf(fmaxf(acc[i][j][q], -30.f), 30.f);
                    float e = __expf(v);
                    acc[i][j][q] = e;
                    pr[i][q >> 1] += e + __fdividef(1.f, e);
                }
        #pragma unroll
        for (int i = 0; i < 2; i++)
            #pragma unroll
            for (int hf = 0; hf < 2; hf++) {
                pr[i][hf] += __shfl_xor_sync(0xffffffffu, pr[i][hf], 1);
                pr[i][hf] += __shfl_xor_sync(0xffffffffu, pr[i][hf], 2);
            }
        if (t == 0) {
            #pragma unroll
            for (int i = 0; i < 2; i++) {
                ss[(wm * 32 + i * 16 + g    ) * 4 + wn] = pr[i][0];
                ss[(wm * 32 + i * 16 + g + 8) * 4 + wn] = pr[i][1];
            }
        }
        __syncthreads();
        float invp[2][2];
        #pragma unroll
        for (int i = 0; i < 2; i++)
            #pragma unroll
            for (int hf = 0; hf < 2; hf++) {
                int r = wm * 32 + i * 16 + g + hf * 8;
                float s = ss[r * 4] + ss[r * 4 + 1] + ss[r * 4 + 2] + ss[r * 4 + 3];
                float sc = 1.f;
                if (seg == 1) sc = pi0[hh * 256 + l0 + r];
                if (seg == 2) sc = pi1[hh * 256 + l0 + r];
                invp[i][hf] = __fdividef(sc, s);
            }

        uint32_t* dstw = (seg == 0) ? (uint32_t*)g_qf_b : (uint32_t*)g_kf_b;
        // pass A: e-side -> words [0,128)
        #pragma unroll
        for (int i = 0; i < 2; i++) {
            int sr = wm * 32 + i * 16;
            #pragma unroll
            for (int j = 0; j < 8; j++) {
                int wc = wn * 32 + j * 4 + t;
                fw[F_STG + (sr + g    ) * 132 + wc] =
                    pk2(acc[i][j][0] * invp[i][0], acc[i][j][1] * invp[i][0]);
                fw[F_STG + (sr + g + 8) * 132 + wc] =
                    pk2(acc[i][j][2] * invp[i][1], acc[i][j][3] * invp[i][1]);
            }
        }
        __syncthreads();
        #pragma unroll
        for (int w = 0; w < 32; w++) {
            int idx = tid + w * 256;
            int r = idx >> 7, wd = idx & 127;
            size_t gw = (size_t)(bh * 256 + l0 + r) * 256 + wd;
            uint32_t val = fw[F_STG + r * 132 + wd];
            if (seg == 2) val = addbf2(dstw[gw], val);
            dstw[gw] = val;
        }
        __syncthreads();
        // pass B: 1/e-side -> words [128,256)
        #pragma unroll
        for (int i = 0; i < 2; i++) {
            int sr = wm * 32 + i * 16;
            #pragma unroll
            for (int j = 0; j < 8; j++) {
                int wc = wn * 32 + j * 4 + t;
                fw[F_STG + (sr + g    ) * 132 + wc] =
                    pk2(__fdividef(invp[i][0], acc[i][j][0]),
                        __fdividef(invp[i][0], acc[i][j][1]));
                fw[F_STG + (sr + g + 8) * 132 + wc] =
                    pk2(__fdividef(invp[i][1], acc[i][j][2]),
                        __fdividef(invp[i][1], acc[i][j][3]));
            }
        }
        __syncthreads();
        #pragma unroll
        for (int w = 0; w < 32; w++) {
            int idx = tid + w * 256;
            int r = idx >> 7, wd = idx & 127;
            size_t gw = (size_t)(bh * 256 + l0 + r) * 256 + 128 + wd;
            uint32_t val = fw[F_STG + r * 132 + wd];
            if (seg == 2) val = addbf2(dstw[gw], val);
            dstw[gw] = val;
        }
        __syncthreads();
    }
}

// ------------------------- attn4: flash-style, all-mma ----------------------
// grid (2, 256). 8 warps; warp wid owns S rows 16*wid..+16 x all 128 cols.
// S mma over 8 K-panels -> mask -> register row-sums (denominator) ->
// repack S fragments to bf16 -> PV mma against V^T. out in regs across sc.
// smem words: Qp[4608] | Kp[4608] | Vt[64*68] | ds[128]
#define A4_Q 0
#define A4_K 4608
#define A4_V 9216
#define A4_D 13568
#define ATTN4_SMEM (13700 * 4)     // 54,800 B

__global__ __launch_bounds__(256) void attn4() {
    extern __shared__ uint32_t aw[];
    float* ds = (float*)(aw + A4_D);
    int tid = threadIdx.x, wid = tid >> 5, lane = tid & 31;
    int g = lane >> 2, t = lane & 3;
    int tc = blockIdx.x, bh = blockIdx.y;
    int hh = bh & 7, b = bh >> 3;
    int lr0 = wid * 16;
    const uint32_t* Qw = (const uint32_t*)g_qf_b;
    const uint32_t* Kw = (const uint32_t*)g_kf_b;
    const uint32_t* Vw = (const uint32_t*)g_vt;

    float out[8][4];
    #pragma unroll
    for (int nd = 0; nd < 8; nd++)
        #pragma unroll
        for (int q = 0; q < 4; q++) out[nd][q] = 0.f;
    float dsum0 = 0.f, dsum1 = 0.f;

    for (int sc = 0; sc <= tc; sc++) {
        __syncthreads();                 // prev PV reads of Vt done
        #pragma unroll
        for (int w = 0; w < 16; w++) {   // V^T tile [64 d][64 words]
            int idx = tid + w * 256;
            int d = idx >> 6, wd = idx & 63;
            aw[A4_V + d * 68 + wd] = Vw[(size_t)(bh * 64 + d) * 128 + sc * 64 + wd];
        }
        float acc[16][4];
        #pragma unroll
        for (int j = 0; j < 16; j++)
            #pragma unroll
            for (int q = 0; q < 4; q++) acc[j][q] = 0.f;

        for (int p = 0; p < 8; p++) {
            __syncthreads();
            #pragma unroll
            for (int w = 0; w < 16; w++) {
                int idx = tid + w * 256;
                int r = idx >> 5, wd = idx & 31;
                aw[A4_Q + r * 36 + wd] =
                    Qw[(size_t)(bh * 256 + tc * 128 + r) * 256 + p * 32 + wd];
                aw[A4_K + r * 36 + wd] =
                    Kw[(size_t)(bh * 256 + sc * 128 + r) * 256 + p * 32 + wd];
            }
            __syncthreads();
            #pragma unroll
            for (int kk = 0; kk < 4; kk++) {
                uint32_t a0 = aw[A4_Q + (lr0 + g    ) * 36 + kk * 8 + t];
                uint32_t a1 = aw[A4_Q + (lr0 + g + 8) * 36 + kk * 8 + t];
                uint32_t a2 = aw[A4_Q + (lr0 + g    ) * 36 + kk * 8 + t + 4];
                uint32_t a3 = aw[A4_Q + (lr0 + g + 8) * 36 + kk * 8 + t + 4];
                #pragma unroll
                for (int j = 0; j < 16; j++) {
                    uint32_t b0 = aw[A4_K + (j * 8 + g) * 36 + kk * 8 + t];
                    uint32_t b1 = aw[A4_K + (j * 8 + g) * 36 + kk * 8 + t + 4];
                    mma16816(acc[j], a0, a1, a2, a3, b0, b1);
                }
            }
        }
        // causal mask (local row/col compare within diagonal chunk)
        if (sc == tc) {
            int lr = lr0 + g;
            #pragma unroll
            for (int j = 0; j < 16; j++) {
                int c0 = j * 8 + 2 * t;
                if (c0     > lr)     acc[j][0] = 0.f;
                if (c0 + 1 > lr)     acc[j][1] = 0.f;
                if (c0     > lr + 8) acc[j][2] = 0.f;
                if (c0 + 1 > lr + 8) acc[j][3] = 0.f;
            }
        }
        // denominator partials (register row-sums)
        #pragma unroll
        for (int j = 0; j < 16; j++) {
            dsum0 += acc[j][0] + acc[j][1];
            dsum1 += acc[j][2] + acc[j][3];
        }
        // PV: repack S to bf16 A-fragments, mma vs V^T
        #pragma unroll
        for (int ks = 0; ks < 8; ks++) {
            uint32_t a0 = pk2(acc[2 * ks][0],     acc[2 * ks][1]);
            uint32_t a1 = pk2(acc[2 * ks][2],     acc[2 * ks][3]);
            uint32_t a2 = pk2(acc[2 * ks + 1][0], acc[2 * ks + 1][1]);
            uint32_t a3 = pk2(acc[2 * ks + 1][2], acc[2 * ks + 1][3]);
            #pragma unroll
            for (int nd = 0; nd < 8; nd++) {
                uint32_t b0 = aw[A4_V + (nd * 8 + g) * 68 + ks * 8 + t];
                uint32_t b1 = aw[A4_V + (nd * 8 + g) * 68 + ks * 8 + t + 4];
                mma16816(out[nd], a0, a1, a2, a3, b0, b1);
            }
        }
    }

    // reduce denominators over quad, publish, scale, write
    dsum0 += __shfl_xor_sync(0xffffffffu, dsum0, 1);
    dsum0 += __shfl_xor_sync(0xffffffffu, dsum0, 2);
    dsum1 += __shfl_xor_sync(0xffffffffu, dsum1, 1);
    dsum1 += __shfl_xor_sync(0xffffffffu, dsum1, 2);
    if (t == 0) { ds[lr0 + g] = dsum0; ds[lr0 + g + 8] = dsum1; }
    __syncthreads();
    int r0 = lr0 + g, r1 = lr0 + g + 8;
    float inv0 = __fdividef(0.125f, ds[r0] + 1e-5f);
    float inv1 = __fdividef(0.125f, ds[r1] + 1e-5f);
    int l0g = tc * 128;
    #pragma unroll
    for (int nd = 0; nd < 8; nd++) {
        int d = nd * 8 + 2 * t;
        __nv_bfloat16* d0 = g_ai_b + (size_t)((l0g + r0) * 32 + b) * 512 + hh * 64 + d;
        __nv_bfloat16* d1 = g_ai_b + (size_t)((l0g + r1) * 32 + b) * 512 + hh * 64 + d;
        *(__nv_bfloat162*)d0 = __floats2bfloat162_rn(out[nd][0] * inv0, out[nd][1] * inv0);
        *(__nv_bfloat162*)d1 = __floats2bfloat162_rn(out[nd][2] * inv1, out[nd][3] * inv1);
    }
}

// ------------------------- residual + LayerNorm ----------------------------
__global__ __launch_bounds__(512) void ln_kernel(
    const float* __restrict__ hin, const float* __restrict__ gamma,
    const float* __restrict__ beta, float* __restrict__ out)
{
    __shared__ float red[32];
    int r = blockIdx.x, j = threadIdx.x;
    float x = g_y[(size_t)r * 512 + j] + hin[(size_t)r * 512 + j];
    float s1 = block_sum<16>(x, red);
    float mu = s1 * (1.f / 512.f);
    float d = x - mu;
    float s2 = block_sum<16>(d * d, red);
    float rstd = rsqrtf(s2 * (1.f / 512.f) + 1e-5f);
    out[(size_t)r * 512 + j] = d * rstd * gamma[j] + beta[j];
}

// ------------------------- launch ------------------------------------------
extern "C" void kernel_launch(void* const* d_in, const int* in_sizes, int n_in,
                              void* d_out, int out_size) {
    const float* h     = (const float*)d_in[0];
    const float* wqkv  = (const float*)d_in[1];
    const float* wo    = (const float*)d_in[2];
    const float* gamma = (const float*)d_in[3];
    const float* beta  = (const float*)d_in[4];
    const float* pi0   = (const float*)d_in[5];
    const float* pi1   = (const float*)d_in[6];
    const float* proj  = (const float*)d_in[7];

    const int GEMM_SMEM = 2 * 4608 * 4;             // 36,864 B
    cudaFuncSetAttribute(feat2, cudaFuncAttributeMaxDynamicSharedMemorySize, FEAT2_SMEM);
    cudaFuncSetAttribute(attn4, cudaFuncAttributeMaxDynamicSharedMemorySize, ATTN4_SMEM);

    conv_h<<<4096, 256>>>(h);
    trans_wqkv<<<dim3(64, 16), dim3(32, 8)>>>(wqkv);
    trans_wo  <<<dim3(16, 16), dim3(32, 8)>>>(wo);
    prep_pT<<<64, 256>>>(proj);
    gemm_qkv<<<dim3(16, 64), 256, GEMM_SMEM>>>();
    feat2<<<dim3(4, 256), 256, FEAT2_SMEM>>>(pi0, pi1);
    attn4<<<dim3(2, 256), 256, ATTN4_SMEM>>>();
    gemm_wo<<<dim3(4, 64), 256, GEMM_SMEM>>>();
    ln_kernel<<<8192, 512>>>(h, gamma, beta, (float*)d_out);
}

// round 10
// speedup vs baseline: 4.7647x; 1.1952x over previous
#include <cuda_runtime.h>
#include <cuda_bf16.h>
#include <cstdint>

// ---------------------------------------------------------------------------
// L=256, B=32, D_MODEL=512, N_HEAD=8, D_HEAD=64, 2m=512
// All GEMM-shaped work on mma.sync m16n8k16 bf16; cp.async ping-pong
// double-buffering hides panel-load latency under the tensor pipe.
// Device globals only bound inside device code (GB300/ATS pitfall).
// ---------------------------------------------------------------------------
#define ROWS 8192
#define BH 256

__device__ float          g_qkv[ROWS * 2048];        // fp32 qkv output
__device__ __nv_bfloat16  g_hb [ROWS * 512];         // h in bf16
__device__ __nv_bfloat16  g_wqkvT[2048 * 512];       // wqkv^T bf16 [N,K]
__device__ __nv_bfloat16  g_woT [512 * 512];         // wo^T bf16 [N,K]
__device__ __nv_bfloat16  g_pT  [256 * 64];          // (C*proj)^T bf16 [m][d]
__device__ __nv_bfloat16  g_qf_b[BH * 256 * 512];    // features bf16
__device__ __nv_bfloat16  g_kf_b[BH * 256 * 512];
__device__ __nv_bfloat16  g_vt [BH * 64 * 256];      // V^T bf16 [bh*64+d][l]
__device__ __nv_bfloat16  g_ai_b[ROWS * 512];        // attn out bf16
__device__ float          g_y  [ROWS * 512];

// ------------------------- helpers ------------------------------------------
__device__ __forceinline__ void mma16816(float c[4],
    uint32_t a0, uint32_t a1, uint32_t a2, uint32_t a3,
    uint32_t b0, uint32_t b1)
{
    asm volatile(
        "mma.sync.aligned.m16n8k16.row.col.f32.bf16.bf16.f32 "
        "{%0,%1,%2,%3}, {%4,%5,%6,%7}, {%8,%9}, {%0,%1,%2,%3};"
        : "+f"(c[0]), "+f"(c[1]), "+f"(c[2]), "+f"(c[3])
        : "r"(a0), "r"(a1), "r"(a2), "r"(a3), "r"(b0), "r"(b1));
}
__device__ __forceinline__ uint32_t pk2(float a, float b) {
    __nv_bfloat162 t = __floats2bfloat162_rn(a, b);
    return *(uint32_t*)&t;
}
__device__ __forceinline__ uint32_t addbf2(uint32_t x, uint32_t y) {
    __nv_bfloat162 a = *(__nv_bfloat162*)&x, b = *(__nv_bfloat162*)&y;
    __nv_bfloat162 r = __hadd2(a, b);
    return *(uint32_t*)&r;
}
__device__ __forceinline__ uint32_t smem_u32(const void* p) {
    uint32_t a;
    asm("{ .reg .u64 t; cvta.to.shared.u64 t, %1; cvt.u32.u64 %0, t; }"
        : "=r"(a) : "l"(p));
    return a;
}
__device__ __forceinline__ void cpa16(uint32_t saddr, const void* g) {
    asm volatile("cp.async.cg.shared.global [%0], [%1], 16;"
                 :: "r"(saddr), "l"(g) : "memory");
}
#define CP_COMMIT() asm volatile("cp.async.commit_group;" ::: "memory")
#define CP_WAIT0()  asm volatile("cp.async.wait_group 0;" ::: "memory")

template<int NW>
__device__ __forceinline__ float block_sum(float v, float* red) {
    #pragma unroll
    for (int o = 16; o; o >>= 1) v += __shfl_xor_sync(0xffffffffu, v, o);
    if ((threadIdx.x & 31) == 0) red[threadIdx.x >> 5] = v;
    __syncthreads();
    if (threadIdx.x < 32) {
        float t = (threadIdx.x < NW) ? red[threadIdx.x] : 0.f;
        #pragma unroll
        for (int o = 16; o; o >>= 1) t += __shfl_xor_sync(0xffffffffu, t, o);
        if (threadIdx.x == 0) red[0] = t;
    }
    __syncthreads();
    float r = red[0];
    __syncthreads();
    return r;
}

// ------------------------- prep kernels ------------------------------------
__global__ __launch_bounds__(256) void conv_h(const float* __restrict__ h) {
    int i = blockIdx.x * 256 + threadIdx.x;
    float4 v = ((const float4*)h)[i];
    struct alignas(8) BF4 { __nv_bfloat162 a, b; };
    BF4 pk;
    pk.a = __floats2bfloat162_rn(v.x, v.y);
    pk.b = __floats2bfloat162_rn(v.z, v.w);
    ((BF4*)g_hb)[i] = pk;
}

__device__ __forceinline__ void transpose_body(
    const float* __restrict__ src, __nv_bfloat16* __restrict__ dst, int K, int N)
{
    __shared__ float t[32][33];
    int bn = blockIdx.x * 32, bk = blockIdx.y * 32;
    #pragma unroll
    for (int i = threadIdx.y; i < 32; i += 8)
        t[i][threadIdx.x] = src[(size_t)(bk + i) * N + bn + threadIdx.x];
    __syncthreads();
    #pragma unroll
    for (int i = threadIdx.y; i < 32; i += 8)
        dst[(size_t)(bn + i) * K + bk + threadIdx.x] =
            __float2bfloat16(t[threadIdx.x][i]);
}
__global__ void trans_wqkv(const float* __restrict__ w) { transpose_body(w, g_wqkvT, 512, 2048); }
__global__ void trans_wo (const float* __restrict__ w) { transpose_body(w, g_woT,  512, 512); }

__global__ __launch_bounds__(256) void prep_pT(const float* __restrict__ proj) {
    int i = blockIdx.x * 256 + threadIdx.x;      // 16384
    int d = i >> 8, m = i & 255;
    g_pT[m * 64 + d] = __float2bfloat16(proj[i] * 0.3535533905932738f);
}

// ------------------------- bf16 tensor-core GEMM (cp.async ping-pong) -------
#define GPAD 36
#define GEMM_SMEM (2 * 9216 * 4)     // 73,728 B

// chunk map: i in [0,1024): r = i>>3, c = (i&7)*4  (4 words = 16B per chunk)
#define GEMM_PREFETCH(p, buf) do {                                             \
    int _b = (buf) * 9216;                                                     \
    _Pragma("unroll")                                                          \
    for (int _j = 0; _j < 4; _j++) {                                           \
        int _i = tid + _j * 256; int _r = _i >> 3, _c = (_i & 7) * 4;          \
        cpa16(sbase + (uint32_t)(_b + _r * GPAD + _c) * 4,                     \
              A32 + (size_t)(bm + _r) * 256 + (p) * 32 + _c);                  \
        cpa16(sbase + (uint32_t)(_b + 4608 + _r * GPAD + _c) * 4,              \
              B32 + (size_t)(bn + _r) * 256 + (p) * 32 + _c);                  \
    }                                                                          \
} while (0)

__device__ __forceinline__ void gemm_body(
    const __nv_bfloat16* __restrict__ A, const __nv_bfloat16* __restrict__ B,
    float* __restrict__ C, int Ntot)
{
    extern __shared__ uint32_t sw[];
    uint32_t sbase = smem_u32(sw);
    int tid = threadIdx.x, wid = tid >> 5, lane = tid & 31;
    int wm = wid >> 2, wn = wid & 3;
    int g = lane >> 2, t = lane & 3;
    int bm = blockIdx.y * 128, bn = blockIdx.x * 128;
    const uint32_t* A32 = (const uint32_t*)A;
    const uint32_t* B32 = (const uint32_t*)B;

    float acc[4][4][4];
    #pragma unroll
    for (int i = 0; i < 4; i++)
        #pragma unroll
        for (int j = 0; j < 4; j++)
            #pragma unroll
            for (int q = 0; q < 4; q++) acc[i][j][q] = 0.f;

    GEMM_PREFETCH(0, 0);
    CP_COMMIT();

    for (int p = 0; p < 8; p++) {
        CP_WAIT0();
        __syncthreads();
        if (p < 7) { GEMM_PREFETCH(p + 1, (p + 1) & 1); CP_COMMIT(); }
        uint32_t* As = sw + (p & 1) * 9216;
        uint32_t* Bs = As + 4608;
        #pragma unroll
        for (int kk = 0; kk < 4; kk++) {
            uint32_t af[4][4], bf[4][2];
            #pragma unroll
            for (int i = 0; i < 4; i++) {
                int r0 = wm * 64 + i * 16;
                af[i][0] = As[(r0 + g    ) * GPAD + kk * 8 + t];
                af[i][1] = As[(r0 + g + 8) * GPAD + kk * 8 + t];
                af[i][2] = As[(r0 + g    ) * GPAD + kk * 8 + t + 4];
                af[i][3] = As[(r0 + g + 8) * GPAD + kk * 8 + t + 4];
            }
            #pragma unroll
            for (int j = 0; j < 4; j++) {
                int n0 = wn * 32 + j * 8;
                bf[j][0] = Bs[(n0 + g) * GPAD + kk * 8 + t];
                bf[j][1] = Bs[(n0 + g) * GPAD + kk * 8 + t + 4];
            }
            #pragma unroll
            for (int i = 0; i < 4; i++)
                #pragma unroll
                for (int j = 0; j < 4; j++)
                    mma16816(acc[i][j], af[i][0], af[i][1], af[i][2], af[i][3],
                             bf[j][0], bf[j][1]);
        }
        __syncthreads();
    }
    #pragma unroll
    for (int i = 0; i < 4; i++) {
        int row = bm + wm * 64 + i * 16 + g;
        #pragma unroll
        for (int j = 0; j < 4; j++) {
            int col = bn + wn * 32 + j * 8 + t * 2;
            *(float2*)&C[(size_t)row * Ntot + col] =
                make_float2(acc[i][j][0], acc[i][j][1]);
            *(float2*)&C[(size_t)(row + 8) * Ntot + col] =
                make_float2(acc[i][j][2], acc[i][j][3]);
        }
    }
}
__global__ __launch_bounds__(256) void gemm_qkv() { gemm_body(g_hb,   g_wqkvT, g_qkv, 2048); }
__global__ __launch_bounds__(256) void gemm_wo()  { gemm_body(g_ai_b, g_woT,   g_y,   512); }

// ------------------------- feat2: FAVOR+ via tensor cores -------------------
#define F_P 0
#define F_X 9216
#define F_V 16128
#define F_STG 18432
#define F_SS 26880
#define FEAT2_SMEM (27136 * 4)     // 108,544 B

__global__ __launch_bounds__(256) void feat2(
    const float* __restrict__ pi0, const float* __restrict__ pi1)
{
    extern __shared__ uint32_t fw[];
    __nv_bfloat16* Xh = (__nv_bfloat16*)(fw + F_X);   // seg*4608 + r*72 + d
    __nv_bfloat16* Vh = (__nv_bfloat16*)(fw + F_V);   // l*72 + d
    float* ss = (float*)(fw + F_SS);
    int tid = threadIdx.x, wid = tid >> 5, lane = tid & 31;
    int wm = wid >> 2, wn = wid & 3;
    int g = lane >> 2, t = lane & 3;
    int l0 = blockIdx.x * 64, bh = blockIdx.y;
    int hh = bh & 7, b = bh >> 3;

    const uint32_t* pTw = (const uint32_t*)g_pT;
    #pragma unroll
    for (int w = 0; w < 32; w++) {
        int idx = tid + w * 256;
        int m = idx >> 5, wd = idx & 31;
        fw[F_P + m * 36 + wd] = pTw[m * 32 + wd];
    }
    #pragma unroll
    for (int w = 0; w < 64; w++) {
        int idx = tid + w * 256;
        int r = idx >> 8, c = idx & 255;
        float v = g_qkv[(size_t)((l0 + r) * 32 + b) * 2048 + hh * 256 + c];
        if (c < 192) {
            int seg = c >> 6, d = c & 63;
            if (seg == 2) v *= 0.7f;
            Xh[seg * 4608 + r * 72 + d] = __float2bfloat16(v);
        } else {
            Vh[r * 72 + (c - 192)] = __float2bfloat16(v);
        }
    }
    __syncthreads();

    #pragma unroll
    for (int w = 0; w < 16; w++) {
        int idx = tid + w * 256;
        int d = idx >> 6, l = idx & 63;
        g_vt[(size_t)(bh * 64 + d) * 256 + l0 + l] = Vh[l * 72 + d];
    }

    for (int seg = 0; seg < 3; seg++) {
        const int XB = F_X + seg * 2304;
        float acc[2][8][4];
        #pragma unroll
        for (int i = 0; i < 2; i++)
            #pragma unroll
            for (int j = 0; j < 8; j++)
                #pragma unroll
                for (int q = 0; q < 4; q++) acc[i][j][q] = 0.f;

        #pragma unroll
        for (int kk = 0; kk < 4; kk++) {
            uint32_t af[2][4], bf[8][2];
            #pragma unroll
            for (int i = 0; i < 2; i++) {
                int r0 = wm * 32 + i * 16;
                af[i][0] = fw[XB + (r0 + g    ) * 36 + kk * 8 + t];
                af[i][1] = fw[XB + (r0 + g + 8) * 36 + kk * 8 + t];
                af[i][2] = fw[XB + (r0 + g    ) * 36 + kk * 8 + t + 4];
                af[i][3] = fw[XB + (r0 + g + 8) * 36 + kk * 8 + t + 4];
            }
            #pragma unroll
            for (int j = 0; j < 8; j++) {
                int n0 = wn * 64 + j * 8;
                bf[j][0] = fw[F_P + (n0 + g) * 36 + kk * 8 + t];
                bf[j][1] = fw[F_P + (n0 + g) * 36 + kk * 8 + t + 4];
            }
            #pragma unroll
            for (int i = 0; i < 2; i++)
                #pragma unroll
                for (int j = 0; j < 8; j++)
                    mma16816(acc[i][j], af[i][0], af[i][1], af[i][2], af[i][3],
                             bf[j][0], bf[j][1]);
        }

        float pr[2][2] = {{0.f, 0.f}, {0.f, 0.f}};
        #pragma unroll
        for (int i = 0; i < 2; i++)
            #pragma unroll
            for (int j = 0; j < 8; j++)
                #pragma unroll
                for (int q = 0; q < 4; q++) {
                    float v = fminf(fmaxf(acc[i][j][q], -30.f), 30.f);
                    float e = __expf(v);
                    acc[i][j][q] = e;
                    pr[i][q >> 1] += e + __fdividef(1.f, e);
                }
        #pragma unroll
        for (int i = 0; i < 2; i++)
            #pragma unroll
            for (int hf = 0; hf < 2; hf++) {
                pr[i][hf] += __shfl_xor_sync(0xffffffffu, pr[i][hf], 1);
                pr[i][hf] += __shfl_xor_sync(0xffffffffu, pr[i][hf], 2);
            }
        if (t == 0) {
            #pragma unroll
            for (int i = 0; i < 2; i++) {
                ss[(wm * 32 + i * 16 + g    ) * 4 + wn] = pr[i][0];
                ss[(wm * 32 + i * 16 + g + 8) * 4 + wn] = pr[i][1];
            }
        }
        __syncthreads();
        float invp[2][2];
        #pragma unroll
        for (int i = 0; i < 2; i++)
            #pragma unroll
            for (int hf = 0; hf < 2; hf++) {
                int r = wm * 32 + i * 16 + g + hf * 8;
                float s = ss[r * 4] + ss[r * 4 + 1] + ss[r * 4 + 2] + ss[r * 4 + 3];
                float sc = 1.f;
                if (seg == 1) sc = pi0[hh * 256 + l0 + r];
                if (seg == 2) sc = pi1[hh * 256 + l0 + r];
                invp[i][hf] = __fdividef(sc, s);
            }

        uint32_t* dstw = (seg == 0) ? (uint32_t*)g_qf_b : (uint32_t*)g_kf_b;
        #pragma unroll
        for (int i = 0; i < 2; i++) {
            int sr = wm * 32 + i * 16;
            #pragma unroll
            for (int j = 0; j < 8; j++) {
                int wc = wn * 32 + j * 4 + t;
                fw[F_STG + (sr + g    ) * 132 + wc] =
                    pk2(acc[i][j][0] * invp[i][0], acc[i][j][1] * invp[i][0]);
                fw[F_STG + (sr + g + 8) * 132 + wc] =
                    pk2(acc[i][j][2] * invp[i][1], acc[i][j][3] * invp[i][1]);
            }
        }
        __syncthreads();
        #pragma unroll
        for (int w = 0; w < 32; w++) {
            int idx = tid + w * 256;
            int r = idx >> 7, wd = idx & 127;
            size_t gw = (size_t)(bh * 256 + l0 + r) * 256 + wd;
            uint32_t val = fw[F_STG + r * 132 + wd];
            if (seg == 2) val = addbf2(dstw[gw], val);
            dstw[gw] = val;
        }
        __syncthreads();
        #pragma unroll
        for (int i = 0; i < 2; i++) {
            int sr = wm * 32 + i * 16;
            #pragma unroll
            for (int j = 0; j < 8; j++) {
                int wc = wn * 32 + j * 4 + t;
                fw[F_STG + (sr + g    ) * 132 + wc] =
                    pk2(__fdividef(invp[i][0], acc[i][j][0]),
                        __fdividef(invp[i][0], acc[i][j][1]));
                fw[F_STG + (sr + g + 8) * 132 + wc] =
                    pk2(__fdividef(invp[i][1], acc[i][j][2]),
                        __fdividef(invp[i][1], acc[i][j][3]));
            }
        }
        __syncthreads();
        #pragma unroll
        for (int w = 0; w < 32; w++) {
            int idx = tid + w * 256;
            int r = idx >> 7, wd = idx & 127;
            size_t gw = (size_t)(bh * 256 + l0 + r) * 256 + 128 + wd;
            uint32_t val = fw[F_STG + r * 132 + wd];
            if (seg == 2) val = addbf2(dstw[gw], val);
            dstw[gw] = val;
        }
        __syncthreads();
    }
}

// ------------------------- attn4: flash-style, all-mma, cp.async ------------
// grid (2, 256). tc = 1 - blockIdx.x (long diagonal blocks first). 8 warps;
// warp owns 16 S-rows x 128 cols. Ping-pong Q/K panel buffers via cp.async.
// smem words: buf0 Q[4608] K[4608] | buf1 Q K | Vt[64*68] | ds[128]
#define A4_V 18432
#define A4_D 22784
#define ATTN4_SMEM ((22784 + 128) * 4)    // 91,648 B

#define AT_PREF(p, buf) do {                                                   \
    int _b = (buf) * 9216;                                                      \
    _Pragma("unroll")                                                           \
    for (int _j = 0; _j < 4; _j++) {                                            \
        int _i = tid + _j * 256; int _r = _i >> 3, _c = (_i & 7) * 4;           \
        cpa16(sbase + (uint32_t)(_b + _r * 36 + _c) * 4,                        \
              Qw + (size_t)(bh * 256 + tc * 128 + _r) * 256 + (p) * 32 + _c);   \
        cpa16(sbase + (uint32_t)(_b + 4608 + _r * 36 + _c) * 4,                 \
              Kw + (size_t)(bh * 256 + sc * 128 + _r) * 256 + (p) * 32 + _c);   \
    }                                                                           \
} while (0)

__global__ __launch_bounds__(256) void attn4() {
    extern __shared__ uint32_t aw[];
    uint32_t sbase = smem_u32(aw);
    float* ds = (float*)(aw + A4_D);
    int tid = threadIdx.x, wid = tid >> 5, lane = tid & 31;
    int g = lane >> 2, t = lane & 3;
    int tc = 1 - (int)blockIdx.x, bh = blockIdx.y;
    int hh = bh & 7, b = bh >> 3;
    int lr0 = wid * 16;
    const uint32_t* Qw = (const uint32_t*)g_qf_b;
    const uint32_t* Kw = (const uint32_t*)g_kf_b;
    const uint32_t* Vw = (const uint32_t*)g_vt;

    float out[8][4];
    #pragma unroll
    for (int nd = 0; nd < 8; nd++)
        #pragma unroll
        for (int q = 0; q < 4; q++) out[nd][q] = 0.f;
    float dsum0 = 0.f, dsum1 = 0.f;

    for (int sc = 0; sc <= tc; sc++) {
        __syncthreads();                 // prev PV reads of Vt / panel bufs done
        // V^T tile (64 d x 64 words) + first panel via cp.async
        #pragma unroll
        for (int _j = 0; _j < 4; _j++) {
            int _i = tid + _j * 256;     // 1024 chunks
            int d = _i >> 4, wd = (_i & 15) * 4;
            cpa16(sbase + (uint32_t)(A4_V + d * 68 + wd) * 4,
                  Vw + (size_t)(bh * 64 + d) * 128 + sc * 64 + wd);
        }
        AT_PREF(0, 0);
        CP_COMMIT();

        float acc[16][4];
        #pragma unroll
        for (int j = 0; j < 16; j++)
            #pragma unroll
            for (int q = 0; q < 4; q++) acc[j][q] = 0.f;

        for (int p = 0; p < 8; p++) {
            CP_WAIT0();
            __syncthreads();
            if (p < 7) { AT_PREF(p + 1, (p + 1) & 1); CP_COMMIT(); }
            const uint32_t* Qp = aw + (p & 1) * 9216;
            const uint32_t* Kp = Qp + 4608;
            #pragma unroll
            for (int kk = 0; kk < 4; kk++) {
                uint32_t a0 = Qp[(lr0 + g    ) * 36 + kk * 8 + t];
                uint32_t a1 = Qp[(lr0 + g + 8) * 36 + kk * 8 + t];
                uint32_t a2 = Qp[(lr0 + g    ) * 36 + kk * 8 + t + 4];
                uint32_t a3 = Qp[(lr0 + g + 8) * 36 + kk * 8 + t + 4];
                #pragma unroll
                for (int j = 0; j < 16; j++) {
                    uint32_t b0 = Kp[(j * 8 + g) * 36 + kk * 8 + t];
                    uint32_t b1 = Kp[(j * 8 + g) * 36 + kk * 8 + t + 4];
                    mma16816(acc[j], a0, a1, a2, a3, b0, b1);
                }
            }
            __syncthreads();
        }
        // causal mask
        if (sc == tc) {
            int lr = lr0 + g;
            #pragma unroll
            for (int j = 0; j < 16; j++) {
                int c0 = j * 8 + 2 * t;
                if (c0     > lr)     acc[j][0] = 0.f;
                if (c0 + 1 > lr)     acc[j][1] = 0.f;
                if (c0     > lr + 8) acc[j][2] = 0.f;
                if (c0 + 1 > lr + 8) acc[j][3] = 0.f;
            }
        }
        // denominator partials
        #pragma unroll
        for (int j = 0; j < 16; j++) {
            dsum0 += acc[j][0] + acc[j][1];
            dsum1 += acc[j][2] + acc[j][3];
        }
        // PV: repack S to bf16 A-fragments, mma vs V^T (in smem)
        #pragma unroll
        for (int ks = 0; ks < 8; ks++) {
            uint32_t a0 = pk2(acc[2 * ks][0],     acc[2 * ks][1]);
            uint32_t a1 = pk2(acc[2 * ks][2],     acc[2 * ks][3]);
            uint32_t a2 = pk2(acc[2 * ks + 1][0], acc[2 * ks + 1][1]);
            uint32_t a3 = pk2(acc[2 * ks + 1][2], acc[2 * ks + 1][3]);
            #pragma unroll
            for (int nd = 0; nd < 8; nd++) {
                uint32_t b0 = aw[A4_V + (nd * 8 + g) * 68 + ks * 8 + t];
                uint32_t b1 = aw[A4_V + (nd * 8 + g) * 68 + ks * 8 + t + 4];
                mma16816(out[nd], a0, a1, a2, a3, b0, b1);
            }
        }
    }

    dsum0 += __shfl_xor_sync(0xffffffffu, dsum0, 1);
    dsum0 += __shfl_xor_sync(0xffffffffu, dsum0, 2);
    dsum1 += __shfl_xor_sync(0xffffffffu, dsum1, 1);
    dsum1 += __shfl_xor_sync(0xffffffffu, dsum1, 2);
    if (t == 0) { ds[lr0 + g] = dsum0; ds[lr0 + g + 8] = dsum1; }
    __syncthreads();
    int r0 = lr0 + g, r1 = lr0 + g + 8;
    float inv0 = __fdividef(0.125f, ds[r0] + 1e-5f);
    float inv1 = __fdividef(0.125f, ds[r1] + 1e-5f);
    int l0g = tc * 128;
    #pragma unroll
    for (int nd = 0; nd < 8; nd++) {
        int d = nd * 8 + 2 * t;
        __nv_bfloat16* d0 = g_ai_b + (size_t)((l0g + r0) * 32 + b) * 512 + hh * 64 + d;
        __nv_bfloat16* d1 = g_ai_b + (size_t)((l0g + r1) * 32 + b) * 512 + hh * 64 + d;
        *(__nv_bfloat162*)d0 = __floats2bfloat162_rn(out[nd][0] * inv0, out[nd][1] * inv0);
        *(__nv_bfloat162*)d1 = __floats2bfloat162_rn(out[nd][2] * inv1, out[nd][3] * inv1);
    }
}

// ------------------------- residual + LayerNorm ----------------------------
__global__ __launch_bounds__(512) void ln_kernel(
    const float* __restrict__ hin, const float* __restrict__ gamma,
    const float* __restrict__ beta, float* __restrict__ out)
{
    __shared__ float red[32];
    int r = blockIdx.x, j = threadIdx.x;
    float x = g_y[(size_t)r * 512 + j] + hin[(size_t)r * 512 + j];
    float s1 = block_sum<16>(x, red);
    float mu = s1 * (1.f / 512.f);
    float d = x - mu;
    float s2 = block_sum<16>(d * d, red);
    float rstd = rsqrtf(s2 * (1.f / 512.f) + 1e-5f);
    out[(size_t)r * 512 + j] = d * rstd * gamma[j] + beta[j];
}

// ------------------------- launch ------------------------------------------
extern "C" void kernel_launch(void* const* d_in, const int* in_sizes, int n_in,
                              void* d_out, int out_size) {
    const float* h     = (const float*)d_in[0];
    const float* wqkv  = (const float*)d_in[1];
    const float* wo    = (const float*)d_in[2];
    const float* gamma = (const float*)d_in[3];
    const float* beta  = (const float*)d_in[4];
    const float* pi0   = (const float*)d_in[5];
    const float* pi1   = (const float*)d_in[6];
    const float* proj  = (const float*)d_in[7];

    cudaFuncSetAttribute(gemm_qkv, cudaFuncAttributeMaxDynamicSharedMemorySize, GEMM_SMEM);
    cudaFuncSetAttribute(gemm_wo,  cudaFuncAttributeMaxDynamicSharedMemorySize, GEMM_SMEM);
    cudaFuncSetAttribute(feat2,    cudaFuncAttributeMaxDynamicSharedMemorySize, FEAT2_SMEM);
    cudaFuncSetAttribute(attn4,    cudaFuncAttributeMaxDynamicSharedMemorySize, ATTN4_SMEM);

    conv_h<<<4096, 256>>>(h);
    trans_wqkv<<<dim3(64, 16), dim3(32, 8)>>>(wqkv);
    trans_wo  <<<dim3(16, 16), dim3(32, 8)>>>(wo);
    prep_pT<<<64, 256>>>(proj);
    gemm_qkv<<<dim3(16, 64), 256, GEMM_SMEM>>>();
    feat2<<<dim3(4, 256), 256, FEAT2_SMEM>>>(pi0, pi1);
    attn4<<<dim3(2, 256), 256, ATTN4_SMEM>>>();
    gemm_wo<<<dim3(4, 64), 256, GEMM_SMEM>>>();
    ln_kernel<<<8192, 512>>>(h, gamma, beta, (float*)d_out);
}

// round 11
// speedup vs baseline: 5.8091x; 1.2192x over previous
#include <cuda_runtime.h>
#include <cuda_bf16.h>
#include <cstdint>

// ---------------------------------------------------------------------------
// L=256, B=32, D_MODEL=512, N_HEAD=8, D_HEAD=64, 2m=512
// All GEMM-shaped work on mma.sync m16n8k16 bf16; cp.async ping-pong.
// R11: bf16 qkv intermediate, fused k1+k2 feature pass (no RMW), merged preps.
// Device globals only bound inside device code (GB300/ATS pitfall).
// ---------------------------------------------------------------------------
#define ROWS 8192
#define BH 256

__device__ __nv_bfloat16  g_qkvb[ROWS * 2048];       // qkv output bf16
__device__ __nv_bfloat16  g_hb [ROWS * 512];         // h in bf16
__device__ __nv_bfloat16  g_wqkvT[2048 * 512];       // wqkv^T bf16 [N,K]
__device__ __nv_bfloat16  g_woT [512 * 512];         // wo^T bf16 [N,K]
__device__ __nv_bfloat16  g_pT  [256 * 64];          // (C*proj)^T bf16 [m][d]
__device__ __nv_bfloat16  g_qf_b[BH * 256 * 512];    // features bf16
__device__ __nv_bfloat16  g_kf_b[BH * 256 * 512];
__device__ __nv_bfloat16  g_vt [BH * 64 * 256];      // V^T bf16 [bh*64+d][l]
__device__ __nv_bfloat16  g_ai_b[ROWS * 512];        // attn out bf16
__device__ float          g_y  [ROWS * 512];

// ------------------------- helpers ------------------------------------------
__device__ __forceinline__ void mma16816(float c[4],
    uint32_t a0, uint32_t a1, uint32_t a2, uint32_t a3,
    uint32_t b0, uint32_t b1)
{
    asm volatile(
        "mma.sync.aligned.m16n8k16.row.col.f32.bf16.bf16.f32 "
        "{%0,%1,%2,%3}, {%4,%5,%6,%7}, {%8,%9}, {%0,%1,%2,%3};"
        : "+f"(c[0]), "+f"(c[1]), "+f"(c[2]), "+f"(c[3])
        : "r"(a0), "r"(a1), "r"(a2), "r"(a3), "r"(b0), "r"(b1));
}
__device__ __forceinline__ uint32_t pk2(float a, float b) {
    __nv_bfloat162 t = __floats2bfloat162_rn(a, b);
    return *(uint32_t*)&t;
}
__device__ __forceinline__ uint32_t smem_u32(const void* p) {
    uint32_t a;
    asm("{ .reg .u64 t; cvta.to.shared.u64 t, %1; cvt.u32.u64 %0, t; }"
        : "=r"(a) : "l"(p));
    return a;
}
__device__ __forceinline__ void cpa16(uint32_t saddr, const void* g) {
    asm volatile("cp.async.cg.shared.global [%0], [%1], 16;"
                 :: "r"(saddr), "l"(g) : "memory");
}
#define CP_COMMIT() asm volatile("cp.async.commit_group;" ::: "memory")
#define CP_WAIT0()  asm volatile("cp.async.wait_group 0;" ::: "memory")

template<int NW>
__device__ __forceinline__ float block_sum(float v, float* red) {
    #pragma unroll
    for (int o = 16; o; o >>= 1) v += __shfl_xor_sync(0xffffffffu, v, o);
    if ((threadIdx.x & 31) == 0) red[threadIdx.x >> 5] = v;
    __syncthreads();
    if (threadIdx.x < 32) {
        float t = (threadIdx.x < NW) ? red[threadIdx.x] : 0.f;
        #pragma unroll
        for (int o = 16; o; o >>= 1) t += __shfl_xor_sync(0xffffffffu, t, o);
        if (threadIdx.x == 0) red[0] = t;
    }
    __syncthreads();
    float r = red[0];
    __syncthreads();
    return r;
}

// ------------------------- merged prep kernel -------------------------------
__device__ __forceinline__ void transpose_dev(
    const float* __restrict__ src, __nv_bfloat16* __restrict__ dst,
    int K, int N, int bx, int by, int tx, int ty, float (*t)[33])
{
    int bn = bx * 32, bk = by * 32;
    #pragma unroll
    for (int i = ty; i < 32; i += 8)
        t[i][tx] = src[(size_t)(bk + i) * N + bn + tx];
    __syncthreads();
    #pragma unroll
    for (int i = ty; i < 32; i += 8)
        dst[(size_t)(bn + i) * K + bk + tx] = __float2bfloat16(t[tx][i]);
}

__global__ __launch_bounds__(256) void prep_all(
    const float* __restrict__ h, const float* __restrict__ wqkv,
    const float* __restrict__ wo, const float* __restrict__ proj)
{
    __shared__ float tbuf[32][33];
    int blk = blockIdx.x, tid = threadIdx.x;
    int tx = tid & 31, ty = tid >> 5;
    if (blk < 4096) {                       // conv_h
        int i = blk * 256 + tid;
        float4 v = ((const float4*)h)[i];
        struct alignas(8) BF4 { __nv_bfloat162 a, b; };
        BF4 pk;
        pk.a = __floats2bfloat162_rn(v.x, v.y);
        pk.b = __floats2bfloat162_rn(v.z, v.w);
        ((BF4*)g_hb)[i] = pk;
    } else if (blk < 5120) {                // trans_wqkv: 64 x 16
        int idx = blk - 4096;
        transpose_dev(wqkv, g_wqkvT, 512, 2048, idx & 63, idx >> 6, tx, ty, tbuf);
    } else if (blk < 5376) {                // trans_wo: 16 x 16
        int idx = blk - 5120;
        transpose_dev(wo, g_woT, 512, 512, idx & 15, idx >> 4, tx, ty, tbuf);
    } else {                                // prep_pT
        int i = (blk - 5376) * 256 + tid;
        int d = i >> 8, m = i & 255;
        g_pT[m * 64 + d] = __float2bfloat16(proj[i] * 0.3535533905932738f);
    }
}

// ------------------------- bf16 tensor-core GEMM (cp.async ping-pong) -------
#define GPAD 36
#define GEMM_SMEM (2 * 9216 * 4)     // 73,728 B

#define GEMM_PREFETCH(p, buf) do {                                             \
    int _b = (buf) * 9216;                                                     \
    _Pragma("unroll")                                                          \
    for (int _j = 0; _j < 4; _j++) {                                           \
        int _i = tid + _j * 256; int _r = _i >> 3, _c = (_i & 7) * 4;          \
        cpa16(sbase + (uint32_t)(_b + _r * GPAD + _c) * 4,                     \
              A32 + (size_t)(bm + _r) * 256 + (p) * 32 + _c);                  \
        cpa16(sbase + (uint32_t)(_b + 4608 + _r * GPAD + _c) * 4,              \
              B32 + (size_t)(bn + _r) * 256 + (p) * 32 + _c);                  \
    }                                                                          \
} while (0)

template<bool BF16OUT>
__device__ __forceinline__ void gemm_body(
    const __nv_bfloat16* __restrict__ A, const __nv_bfloat16* __restrict__ B,
    float* __restrict__ C, uint32_t* __restrict__ Cb, int Ntot)
{
    extern __shared__ uint32_t sw[];
    uint32_t sbase = smem_u32(sw);
    int tid = threadIdx.x, wid = tid >> 5, lane = tid & 31;
    int wm = wid >> 2, wn = wid & 3;
    int g = lane >> 2, t = lane & 3;
    int bm = blockIdx.y * 128, bn = blockIdx.x * 128;
    const uint32_t* A32 = (const uint32_t*)A;
    const uint32_t* B32 = (const uint32_t*)B;

    float acc[4][4][4];
    #pragma unroll
    for (int i = 0; i < 4; i++)
        #pragma unroll
        for (int j = 0; j < 4; j++)
            #pragma unroll
            for (int q = 0; q < 4; q++) acc[i][j][q] = 0.f;

    GEMM_PREFETCH(0, 0);
    CP_COMMIT();

    for (int p = 0; p < 8; p++) {
        CP_WAIT0();
        __syncthreads();
        if (p < 7) { GEMM_PREFETCH(p + 1, (p + 1) & 1); CP_COMMIT(); }
        uint32_t* As = sw + (p & 1) * 9216;
        uint32_t* Bs = As + 4608;
        #pragma unroll
        for (int kk = 0; kk < 4; kk++) {
            uint32_t af[4][4], bf[4][2];
            #pragma unroll
            for (int i = 0; i < 4; i++) {
                int r0 = wm * 64 + i * 16;
                af[i][0] = As[(r0 + g    ) * GPAD + kk * 8 + t];
                af[i][1] = As[(r0 + g + 8) * GPAD + kk * 8 + t];
                af[i][2] = As[(r0 + g    ) * GPAD + kk * 8 + t + 4];
                af[i][3] = As[(r0 + g + 8) * GPAD + kk * 8 + t + 4];
            }
            #pragma unroll
            for (int j = 0; j < 4; j++) {
                int n0 = wn * 32 + j * 8;
                bf[j][0] = Bs[(n0 + g) * GPAD + kk * 8 + t];
                bf[j][1] = Bs[(n0 + g) * GPAD + kk * 8 + t + 4];
            }
            #pragma unroll
            for (int i = 0; i < 4; i++)
                #pragma unroll
                for (int j = 0; j < 4; j++)
                    mma16816(acc[i][j], af[i][0], af[i][1], af[i][2], af[i][3],
                             bf[j][0], bf[j][1]);
        }
        __syncthreads();
    }
    #pragma unroll
    for (int i = 0; i < 4; i++) {
        int row = bm + wm * 64 + i * 16 + g;
        #pragma unroll
        for (int j = 0; j < 4; j++) {
            if (BF16OUT) {
                int widx = (bn >> 1) + wn * 16 + j * 4 + t;
                Cb[(size_t)row * (Ntot >> 1) + widx] = pk2(acc[i][j][0], acc[i][j][1]);
                Cb[(size_t)(row + 8) * (Ntot >> 1) + widx] = pk2(acc[i][j][2], acc[i][j][3]);
            } else {
                int col = bn + wn * 32 + j * 8 + t * 2;
                *(float2*)&C[(size_t)row * Ntot + col] =
                    make_float2(acc[i][j][0], acc[i][j][1]);
                *(float2*)&C[(size_t)(row + 8) * Ntot + col] =
                    make_float2(acc[i][j][2], acc[i][j][3]);
            }
        }
    }
}
__global__ __launch_bounds__(256) void gemm_qkv() {
    gemm_body<true>(g_hb, g_wqkvT, nullptr, (uint32_t*)g_qkvb, 2048);
}
__global__ __launch_bounds__(256) void gemm_wo() {
    gemm_body<false>(g_ai_b, g_woT, g_y, nullptr, 512);
}

// ------------------------- feat2: FAVOR+ via tensor cores -------------------
// grid (4, 256). q-seg as before; k1+k2 fused in one pass (no global RMW).
// smem words: P[9216] | X[3*2304] | V[2304] | STG[8448] | SS[512]
#define F_P 0
#define F_X 9216
#define F_V 16128
#define F_STG 18432
#define F_SS 26880
#define FEAT2_SMEM (27392 * 4)     // 109,568 B

__global__ __launch_bounds__(256) void feat2(
    const float* __restrict__ pi0, const float* __restrict__ pi1)
{
    extern __shared__ uint32_t fw[];
    __nv_bfloat16* Vh = (__nv_bfloat16*)(fw + F_V);   // l*72 + d
    float* ss = (float*)(fw + F_SS);
    int tid = threadIdx.x, wid = tid >> 5, lane = tid & 31;
    int wm = wid >> 2, wn = wid & 3;
    int g = lane >> 2, t = lane & 3;
    int l0 = blockIdx.x * 64, bh = blockIdx.y;
    int hh = bh & 7, b = bh >> 3;

    // load P^T
    const uint32_t* pTw = (const uint32_t*)g_pT;
    #pragma unroll
    for (int w = 0; w < 32; w++) {
        int idx = tid + w * 256;
        int m = idx >> 5, wd = idx & 31;
        fw[F_P + m * 36 + wd] = pTw[m * 32 + wd];
    }
    // load X (q,k1,0.7*k2) + V from bf16 qkv (word loads)
    const uint32_t* Xg = (const uint32_t*)g_qkvb;
    const __nv_bfloat162 c07 = __float2bfloat162_rn(0.7f);
    #pragma unroll
    for (int w = 0; w < 32; w++) {
        int idx = tid + w * 256;
        int r = idx >> 7, wc = idx & 127;
        uint32_t word = Xg[(size_t)((l0 + r) * 32 + b) * 1024 + hh * 128 + wc];
        if (wc < 96) {
            int seg = wc >> 5, cc = wc & 31;
            if (seg == 2) {
                __nv_bfloat162 tt = *(__nv_bfloat162*)&word;
                tt = __hmul2(tt, c07);
                word = *(uint32_t*)&tt;
            }
            fw[F_X + seg * 2304 + r * 36 + cc] = word;
        } else {
            fw[F_V + r * 36 + (wc - 96)] = word;
        }
    }
    __syncthreads();

    // V^T -> global
    #pragma unroll
    for (int w = 0; w < 16; w++) {
        int idx = tid + w * 256;
        int d = idx >> 6, l = idx & 63;
        g_vt[(size_t)(bh * 64 + d) * 256 + l0 + l] = Vh[l * 72 + d];
    }

    // ===================== seg0: q features =====================
    {
        float acc[2][8][4];
        #pragma unroll
        for (int i = 0; i < 2; i++)
            #pragma unroll
            for (int j = 0; j < 8; j++)
                #pragma unroll
                for (int q = 0; q < 4; q++) acc[i][j][q] = 0.f;
        #pragma unroll
        for (int kk = 0; kk < 4; kk++) {
            uint32_t af[2][4], bf[8][2];
            #pragma unroll
            for (int i = 0; i < 2; i++) {
                int r0 = wm * 32 + i * 16;
                af[i][0] = fw[F_X + (r0 + g    ) * 36 + kk * 8 + t];
                af[i][1] = fw[F_X + (r0 + g + 8) * 36 + kk * 8 + t];
                af[i][2] = fw[F_X + (r0 + g    ) * 36 + kk * 8 + t + 4];
                af[i][3] = fw[F_X + (r0 + g + 8) * 36 + kk * 8 + t + 4];
            }
            #pragma unroll
            for (int j = 0; j < 8; j++) {
                int n0 = wn * 64 + j * 8;
                bf[j][0] = fw[F_P + (n0 + g) * 36 + kk * 8 + t];
                bf[j][1] = fw[F_P + (n0 + g) * 36 + kk * 8 + t + 4];
            }
            #pragma unroll
            for (int i = 0; i < 2; i++)
                #pragma unroll
                for (int j = 0; j < 8; j++)
                    mma16816(acc[i][j], af[i][0], af[i][1], af[i][2], af[i][3],
                             bf[j][0], bf[j][1]);
        }
        float pr[2][2] = {{0.f, 0.f}, {0.f, 0.f}};
        #pragma unroll
        for (int i = 0; i < 2; i++)
            #pragma unroll
            for (int j = 0; j < 8; j++)
                #pragma unroll
                for (int q = 0; q < 4; q++) {
                    float v = fminf(fmaxf(acc[i][j][q], -30.f), 30.f);
                    float e = __expf(v);
                    acc[i][j][q] = e;
                    pr[i][q >> 1] += e + __fdividef(1.f, e);
                }
        #pragma unroll
        for (int i = 0; i < 2; i++)
            #pragma unroll
            for (int hf = 0; hf < 2; hf++) {
                pr[i][hf] += __shfl_xor_sync(0xffffffffu, pr[i][hf], 1);
                pr[i][hf] += __shfl_xor_sync(0xffffffffu, pr[i][hf], 2);
            }
        if (t == 0) {
            #pragma unroll
            for (int i = 0; i < 2; i++) {
                ss[(wm * 32 + i * 16 + g    ) * 4 + wn] = pr[i][0];
                ss[(wm * 32 + i * 16 + g + 8) * 4 + wn] = pr[i][1];
            }
        }
        __syncthreads();
        float invp[2][2];
        #pragma unroll
        for (int i = 0; i < 2; i++)
            #pragma unroll
            for (int hf = 0; hf < 2; hf++) {
                int r = wm * 32 + i * 16 + g + hf * 8;
                float s = ss[r * 4] + ss[r * 4 + 1] + ss[r * 4 + 2] + ss[r * 4 + 3];
                invp[i][hf] = __fdividef(1.f, s);
            }
        uint32_t* dstw = (uint32_t*)g_qf_b;
        // e-side
        #pragma unroll
        for (int i = 0; i < 2; i++) {
            int sr = wm * 32 + i * 16;
            #pragma unroll
            for (int j = 0; j < 8; j++) {
                int wc = wn * 32 + j * 4 + t;
                fw[F_STG + (sr + g    ) * 132 + wc] =
                    pk2(acc[i][j][0] * invp[i][0], acc[i][j][1] * invp[i][0]);
                fw[F_STG + (sr + g + 8) * 132 + wc] =
                    pk2(acc[i][j][2] * invp[i][1], acc[i][j][3] * invp[i][1]);
            }
        }
        __syncthreads();
        #pragma unroll
        for (int w = 0; w < 32; w++) {
            int idx = tid + w * 256;
            int r = idx >> 7, wd = idx & 127;
            dstw[(size_t)(bh * 256 + l0 + r) * 256 + wd] = fw[F_STG + r * 132 + wd];
        }
        __syncthreads();
        // 1/e-side
        #pragma unroll
        for (int i = 0; i < 2; i++) {
            int sr = wm * 32 + i * 16;
            #pragma unroll
            for (int j = 0; j < 8; j++) {
                int wc = wn * 32 + j * 4 + t;
                fw[F_STG + (sr + g    ) * 132 + wc] =
                    pk2(__fdividef(invp[i][0], acc[i][j][0]),
                        __fdividef(invp[i][0], acc[i][j][1]));
                fw[F_STG + (sr + g + 8) * 132 + wc] =
                    pk2(__fdividef(invp[i][1], acc[i][j][2]),
                        __fdividef(invp[i][1], acc[i][j][3]));
            }
        }
        __syncthreads();
        #pragma unroll
        for (int w = 0; w < 32; w++) {
            int idx = tid + w * 256;
            int r = idx >> 7, wd = idx & 127;
            dstw[(size_t)(bh * 256 + l0 + r) * 256 + 128 + wd] = fw[F_STG + r * 132 + wd];
        }
        __syncthreads();
    }

    // ===================== fused seg1+seg2: k features =====================
    {
        float a1[2][8][4], a2[2][8][4];
        #pragma unroll
        for (int i = 0; i < 2; i++)
            #pragma unroll
            for (int j = 0; j < 8; j++)
                #pragma unroll
                for (int q = 0; q < 4; q++) { a1[i][j][q] = 0.f; a2[i][j][q] = 0.f; }
        #pragma unroll
        for (int kk = 0; kk < 4; kk++) {
            uint32_t af1[2][4], af2[2][4], bf[8][2];
            #pragma unroll
            for (int i = 0; i < 2; i++) {
                int r0 = wm * 32 + i * 16;
                af1[i][0] = fw[F_X + 2304 + (r0 + g    ) * 36 + kk * 8 + t];
                af1[i][1] = fw[F_X + 2304 + (r0 + g + 8) * 36 + kk * 8 + t];
                af1[i][2] = fw[F_X + 2304 + (r0 + g    ) * 36 + kk * 8 + t + 4];
                af1[i][3] = fw[F_X + 2304 + (r0 + g + 8) * 36 + kk * 8 + t + 4];
                af2[i][0] = fw[F_X + 4608 + (r0 + g    ) * 36 + kk * 8 + t];
                af2[i][1] = fw[F_X + 4608 + (r0 + g + 8) * 36 + kk * 8 + t];
                af2[i][2] = fw[F_X + 4608 + (r0 + g    ) * 36 + kk * 8 + t + 4];
                af2[i][3] = fw[F_X + 4608 + (r0 + g + 8) * 36 + kk * 8 + t + 4];
            }
            #pragma unroll
            for (int j = 0; j < 8; j++) {
                int n0 = wn * 64 + j * 8;
                bf[j][0] = fw[F_P + (n0 + g) * 36 + kk * 8 + t];
                bf[j][1] = fw[F_P + (n0 + g) * 36 + kk * 8 + t + 4];
            }
            #pragma unroll
            for (int i = 0; i < 2; i++)
                #pragma unroll
                for (int j = 0; j < 8; j++) {
                    mma16816(a1[i][j], af1[i][0], af1[i][1], af1[i][2], af1[i][3],
                             bf[j][0], bf[j][1]);
                    mma16816(a2[i][j], af2[i][0], af2[i][1], af2[i][2], af2[i][3],
                             bf[j][0], bf[j][1]);
                }
        }
        float pr1[2][2] = {{0.f, 0.f}, {0.f, 0.f}};
        float pr2[2][2] = {{0.f, 0.f}, {0.f, 0.f}};
        #pragma unroll
        for (int i = 0; i < 2; i++)
            #pragma unroll
            for (int j = 0; j < 8; j++)
                #pragma unroll
                for (int q = 0; q < 4; q++) {
                    float v1 = fminf(fmaxf(a1[i][j][q], -30.f), 30.f);
                    float e1 = __expf(v1);
                    a1[i][j][q] = e1;
                    pr1[i][q >> 1] += e1 + __fdividef(1.f, e1);
                    float v2 = fminf(fmaxf(a2[i][j][q], -30.f), 30.f);
                    float e2 = __expf(v2);
                    a2[i][j][q] = e2;
                    pr2[i][q >> 1] += e2 + __fdividef(1.f, e2);
                }
        #pragma unroll
        for (int i = 0; i < 2; i++)
            #pragma unroll
            for (int hf = 0; hf < 2; hf++) {
                pr1[i][hf] += __shfl_xor_sync(0xffffffffu, pr1[i][hf], 1);
                pr1[i][hf] += __shfl_xor_sync(0xffffffffu, pr1[i][hf], 2);
                pr2[i][hf] += __shfl_xor_sync(0xffffffffu, pr2[i][hf], 1);
                pr2[i][hf] += __shfl_xor_sync(0xffffffffu, pr2[i][hf], 2);
            }
        if (t == 0) {
            #pragma unroll
            for (int i = 0; i < 2; i++) {
                int ra = wm * 32 + i * 16 + g, rb = ra + 8;
                ss[ra * 4 + wn]       = pr1[i][0];
                ss[rb * 4 + wn]       = pr1[i][1];
                ss[256 + ra * 4 + wn] = pr2[i][0];
                ss[256 + rb * 4 + wn] = pr2[i][1];
            }
        }
        __syncthreads();
        float iv1[2][2], iv2[2][2];
        #pragma unroll
        for (int i = 0; i < 2; i++)
            #pragma unroll
            for (int hf = 0; hf < 2; hf++) {
                int r = wm * 32 + i * 16 + g + hf * 8;
                float s1 = ss[r * 4] + ss[r * 4 + 1] + ss[r * 4 + 2] + ss[r * 4 + 3];
                float s2 = ss[256 + r * 4] + ss[256 + r * 4 + 1]
                         + ss[256 + r * 4 + 2] + ss[256 + r * 4 + 3];
                iv1[i][hf] = __fdividef(pi0[hh * 256 + l0 + r], s1);
                iv2[i][hf] = __fdividef(pi1[hh * 256 + l0 + r], s2);
            }
        uint32_t* dstw = (uint32_t*)g_kf_b;
        // e-side combined
        #pragma unroll
        for (int i = 0; i < 2; i++) {
            int sr = wm * 32 + i * 16;
            #pragma unroll
            for (int j = 0; j < 8; j++) {
                int wc = wn * 32 + j * 4 + t;
                fw[F_STG + (sr + g    ) * 132 + wc] =
                    pk2(a1[i][j][0] * iv1[i][0] + a2[i][j][0] * iv2[i][0],
                        a1[i][j][1] * iv1[i][0] + a2[i][j][1] * iv2[i][0]);
                fw[F_STG + (sr + g + 8) * 132 + wc] =
                    pk2(a1[i][j][2] * iv1[i][1] + a2[i][j][2] * iv2[i][1],
                        a1[i][j][3] * iv1[i][1] + a2[i][j][3] * iv2[i][1]);
            }
        }
        __syncthreads();
        #pragma unroll
        for (int w = 0; w < 32; w++) {
            int idx = tid + w * 256;
            int r = idx >> 7, wd = idx & 127;
            dstw[(size_t)(bh * 256 + l0 + r) * 256 + wd] = fw[F_STG + r * 132 + wd];
        }
        __syncthreads();
        // 1/e-side combined
        #pragma unroll
        for (int i = 0; i < 2; i++) {
            int sr = wm * 32 + i * 16;
            #pragma unroll
            for (int j = 0; j < 8; j++) {
                int wc = wn * 32 + j * 4 + t;
                fw[F_STG + (sr + g    ) * 132 + wc] =
                    pk2(__fdividef(iv1[i][0], a1[i][j][0]) + __fdividef(iv2[i][0], a2[i][j][0]),
                        __fdividef(iv1[i][0], a1[i][j][1]) + __fdividef(iv2[i][0], a2[i][j][1]));
                fw[F_STG + (sr + g + 8) * 132 + wc] =
                    pk2(__fdividef(iv1[i][1], a1[i][j][2]) + __fdividef(iv2[i][1], a2[i][j][2]),
                        __fdividef(iv1[i][1], a1[i][j][3]) + __fdividef(iv2[i][1], a2[i][j][3]));
            }
        }
        __syncthreads();
        #pragma unroll
        for (int w = 0; w < 32; w++) {
            int idx = tid + w * 256;
            int r = idx >> 7, wd = idx & 127;
            dstw[(size_t)(bh * 256 + l0 + r) * 256 + 128 + wd] = fw[F_STG + r * 132 + wd];
        }
    }
}

// ------------------------- attn4: flash-style, all-mma, cp.async ------------
#define A4_V 18432
#define A4_D 22784
#define ATTN4_SMEM ((22784 + 128) * 4)    // 91,648 B

#define AT_PREF(p, buf) do {                                                   \
    int _b = (buf) * 9216;                                                      \
    _Pragma("unroll")                                                           \
    for (int _j = 0; _j < 4; _j++) {                                            \
        int _i = tid + _j * 256; int _r = _i >> 3, _c = (_i & 7) * 4;           \
        cpa16(sbase + (uint32_t)(_b + _r * 36 + _c) * 4,                        \
              Qw + (size_t)(bh * 256 + tc * 128 + _r) * 256 + (p) * 32 + _c);   \
        cpa16(sbase + (uint32_t)(_b + 4608 + _r * 36 + _c) * 4,                 \
              Kw + (size_t)(bh * 256 + sc * 128 + _r) * 256 + (p) * 32 + _c);   \
    }                                                                           \
} while (0)

__global__ __launch_bounds__(256) void attn4() {
    extern __shared__ uint32_t aw[];
    uint32_t sbase = smem_u32(aw);
    float* ds = (float*)(aw + A4_D);
    int tid = threadIdx.x, wid = tid >> 5, lane = tid & 31;
    int g = lane >> 2, t = lane & 3;
    int tc = 1 - (int)blockIdx.x, bh = blockIdx.y;
    int hh = bh & 7, b = bh >> 3;
    int lr0 = wid * 16;
    const uint32_t* Qw = (const uint32_t*)g_qf_b;
    const uint32_t* Kw = (const uint32_t*)g_kf_b;
    const uint32_t* Vw = (const uint32_t*)g_vt;

    float out[8][4];
    #pragma unroll
    for (int nd = 0; nd < 8; nd++)
        #pragma unroll
        for (int q = 0; q < 4; q++) out[nd][q] = 0.f;
    float dsum0 = 0.f, dsum1 = 0.f;

    for (int sc = 0; sc <= tc; sc++) {
        __syncthreads();
        #pragma unroll
        for (int _j = 0; _j < 4; _j++) {
            int _i = tid + _j * 256;
            int d = _i >> 4, wd = (_i & 15) * 4;
            cpa16(sbase + (uint32_t)(A4_V + d * 68 + wd) * 4,
                  Vw + (size_t)(bh * 64 + d) * 128 + sc * 64 + wd);
        }
        AT_PREF(0, 0);
        CP_COMMIT();

        float acc[16][4];
        #pragma unroll
        for (int j = 0; j < 16; j++)
            #pragma unroll
            for (int q = 0; q < 4; q++) acc[j][q] = 0.f;

        for (int p = 0; p < 8; p++) {
            CP_WAIT0();
            __syncthreads();
            if (p < 7) { AT_PREF(p + 1, (p + 1) & 1); CP_COMMIT(); }
            const uint32_t* Qp = aw + (p & 1) * 9216;
            const uint32_t* Kp = Qp + 4608;
            #pragma unroll
            for (int kk = 0; kk < 4; kk++) {
                uint32_t a0 = Qp[(lr0 + g    ) * 36 + kk * 8 + t];
                uint32_t a1 = Qp[(lr0 + g + 8) * 36 + kk * 8 + t];
                uint32_t a2 = Qp[(lr0 + g    ) * 36 + kk * 8 + t + 4];
                uint32_t a3 = Qp[(lr0 + g + 8) * 36 + kk * 8 + t + 4];
                #pragma unroll
                for (int j = 0; j < 16; j++) {
                    uint32_t b0 = Kp[(j * 8 + g) * 36 + kk * 8 + t];
                    uint32_t b1 = Kp[(j * 8 + g) * 36 + kk * 8 + t + 4];
                    mma16816(acc[j], a0, a1, a2, a3, b0, b1);
                }
            }
            __syncthreads();
        }
        if (sc == tc) {
            int lr = lr0 + g;
            #pragma unroll
            for (int j = 0; j < 16; j++) {
                int c0 = j * 8 + 2 * t;
                if (c0     > lr)     acc[j][0] = 0.f;
                if (c0 + 1 > lr)     acc[j][1] = 0.f;
                if (c0     > lr + 8) acc[j][2] = 0.f;
                if (c0 + 1 > lr + 8) acc[j][3] = 0.f;
            }
        }
        #pragma unroll
        for (int j = 0; j < 16; j++) {
            dsum0 += acc[j][0] + acc[j][1];
            dsum1 += acc[j][2] + acc[j][3];
        }
        #pragma unroll
        for (int ks = 0; ks < 8; ks++) {
            uint32_t a0 = pk2(acc[2 * ks][0],     acc[2 * ks][1]);
            uint32_t a1 = pk2(acc[2 * ks][2],     acc[2 * ks][3]);
            uint32_t a2 = pk2(acc[2 * ks + 1][0], acc[2 * ks + 1][1]);
            uint32_t a3 = pk2(acc[2 * ks + 1][2], acc[2 * ks + 1][3]);
            #pragma unroll
            for (int nd = 0; nd < 8; nd++) {
                uint32_t b0 = aw[A4_V + (nd * 8 + g) * 68 + ks * 8 + t];
                uint32_t b1 = aw[A4_V + (nd * 8 + g) * 68 + ks * 8 + t + 4];
                mma16816(out[nd], a0, a1, a2, a3, b0, b1);
            }
        }
    }

    dsum0 += __shfl_xor_sync(0xffffffffu, dsum0, 1);
    dsum0 += __shfl_xor_sync(0xffffffffu, dsum0, 2);
    dsum1 += __shfl_xor_sync(0xffffffffu, dsum1, 1);
    dsum1 += __shfl_xor_sync(0xffffffffu, dsum1, 2);
    if (t == 0) { ds[lr0 + g] = dsum0; ds[lr0 + g + 8] = dsum1; }
    __syncthreads();
    int r0 = lr0 + g, r1 = lr0 + g + 8;
    float inv0 = __fdividef(0.125f, ds[r0] + 1e-5f);
    float inv1 = __fdividef(0.125f, ds[r1] + 1e-5f);
    int l0g = tc * 128;
    #pragma unroll
    for (int nd = 0; nd < 8; nd++) {
        int d = nd * 8 + 2 * t;
        __nv_bfloat16* d0 = g_ai_b + (size_t)((l0g + r0) * 32 + b) * 512 + hh * 64 + d;
        __nv_bfloat16* d1 = g_ai_b + (size_t)((l0g + r1) * 32 + b) * 512 + hh * 64 + d;
        *(__nv_bfloat162*)d0 = __floats2bfloat162_rn(out[nd][0] * inv0, out[nd][1] * inv0);
        *(__nv_bfloat162*)d1 = __floats2bfloat162_rn(out[nd][2] * inv1, out[nd][3] * inv1);
    }
}

// ------------------------- residual + LayerNorm ----------------------------
__global__ __launch_bounds__(512) void ln_kernel(
    const float* __restrict__ hin, const float* __restrict__ gamma,
    const float* __restrict__ beta, float* __restrict__ out)
{
    __shared__ float red[32];
    int r = blockIdx.x, j = threadIdx.x;
    float x = g_y[(size_t)r * 512 + j] + hin[(size_t)r * 512 + j];
    float s1 = block_sum<16>(x, red);
    float mu = s1 * (1.f / 512.f);
    float d = x - mu;
    float s2 = block_sum<16>(d * d, red);
    float rstd = rsqrtf(s2 * (1.f / 512.f) + 1e-5f);
    out[(size_t)r * 512 + j] = d * rstd * gamma[j] + beta[j];
}

// ------------------------- launch ------------------------------------------
extern "C" void kernel_launch(void* const* d_in, const int* in_sizes, int n_in,
                              void* d_out, int out_size) {
    const float* h     = (const float*)d_in[0];
    const float* wqkv  = (const float*)d_in[1];
    const float* wo    = (const float*)d_in[2];
    const float* gamma = (const float*)d_in[3];
    const float* beta  = (const float*)d_in[4];
    const float* pi0   = (const float*)d_in[5];
    const float* pi1   = (const float*)d_in[6];
    const float* proj  = (const float*)d_in[7];

    cudaFuncSetAttribute(gemm_qkv, cudaFuncAttributeMaxDynamicSharedMemorySize, GEMM_SMEM);
    cudaFuncSetAttribute(gemm_wo,  cudaFuncAttributeMaxDynamicSharedMemorySize, GEMM_SMEM);
    cudaFuncSetAttribute(feat2,    cudaFuncAttributeMaxDynamicSharedMemorySize, FEAT2_SMEM);
    cudaFuncSetAttribute(attn4,    cudaFuncAttributeMaxDynamicSharedMemorySize, ATTN4_SMEM);

    prep_all<<<5440, 256>>>(h, wqkv, wo, proj);
    gemm_qkv<<<dim3(16, 64), 256, GEMM_SMEM>>>();
    feat2<<<dim3(4, 256), 256, FEAT2_SMEM>>>(pi0, pi1);
    attn4<<<dim3(2, 256), 256, ATTN4_SMEM>>>();
    gemm_wo<<<dim3(4, 64), 256, GEMM_SMEM>>>();
    ln_kernel<<<8192, 512>>>(h, gamma, beta, (float*)d_out);
}

// round 12
// speedup vs baseline: 6.2572x; 1.0771x over previous
#include <cuda_runtime.h>
#include <cuda_bf16.h>
#include <cstdint>

// ---------------------------------------------------------------------------
// L=256, B=32, D_MODEL=512, N_HEAD=8, D_HEAD=64, 2m=512
// All GEMM-shaped work on mma.sync m16n8k16 bf16; cp.async ping-pong;
// ldmatrix fragment loads (R12). Device globals only bound in device code.
// ---------------------------------------------------------------------------
#define ROWS 8192
#define BH 256

__device__ __nv_bfloat16  g_qkvb[ROWS * 2048];       // qkv output bf16
__device__ __nv_bfloat16  g_hb [ROWS * 512];         // h in bf16
__device__ __nv_bfloat16  g_wqkvT[2048 * 512];       // wqkv^T bf16 [N,K]
__device__ __nv_bfloat16  g_woT [512 * 512];         // wo^T bf16 [N,K]
__device__ __nv_bfloat16  g_pT  [256 * 64];          // (C*proj)^T bf16 [m][d]
__device__ __nv_bfloat16  g_qf_b[BH * 256 * 512];    // features bf16
__device__ __nv_bfloat16  g_kf_b[BH * 256 * 512];
__device__ __nv_bfloat16  g_vt [BH * 64 * 256];      // V^T bf16 [bh*64+d][l]
__device__ __nv_bfloat16  g_ai_b[ROWS * 512];        // attn out bf16
__device__ __nv_bfloat16  g_yb [ROWS * 512];         // w_o GEMM result bf16

// ------------------------- helpers ------------------------------------------
__device__ __forceinline__ void mma16816(float c[4],
    uint32_t a0, uint32_t a1, uint32_t a2, uint32_t a3,
    uint32_t b0, uint32_t b1)
{
    asm volatile(
        "mma.sync.aligned.m16n8k16.row.col.f32.bf16.bf16.f32 "
        "{%0,%1,%2,%3}, {%4,%5,%6,%7}, {%8,%9}, {%0,%1,%2,%3};"
        : "+f"(c[0]), "+f"(c[1]), "+f"(c[2]), "+f"(c[3])
        : "r"(a0), "r"(a1), "r"(a2), "r"(a3), "r"(b0), "r"(b1));
}
__device__ __forceinline__ void ldsm4(uint32_t* r, uint32_t addr) {
    asm volatile("ldmatrix.sync.aligned.m8n8.x4.shared.b16 {%0,%1,%2,%3}, [%4];"
        : "=r"(r[0]), "=r"(r[1]), "=r"(r[2]), "=r"(r[3]) : "r"(addr));
}
__device__ __forceinline__ uint32_t pk2(float a, float b) {
    __nv_bfloat162 t = __floats2bfloat162_rn(a, b);
    return *(uint32_t*)&t;
}
__device__ __forceinline__ uint32_t smem_u32(const void* p) {
    uint32_t a;
    asm("{ .reg .u64 t; cvta.to.shared.u64 t, %1; cvt.u32.u64 %0, t; }"
        : "=r"(a) : "l"(p));
    return a;
}
__device__ __forceinline__ void cpa16(uint32_t saddr, const void* g) {
    asm volatile("cp.async.cg.shared.global [%0], [%1], 16;"
                 :: "r"(saddr), "l"(g) : "memory");
}
#define CP_COMMIT() asm volatile("cp.async.commit_group;" ::: "memory")
#define CP_WAIT0()  asm volatile("cp.async.wait_group 0;" ::: "memory")

template<int NW>
__device__ __forceinline__ float block_sum(float v, float* red) {
    #pragma unroll
    for (int o = 16; o; o >>= 1) v += __shfl_xor_sync(0xffffffffu, v, o);
    if ((threadIdx.x & 31) == 0) red[threadIdx.x >> 5] = v;
    __syncthreads();
    if (threadIdx.x < 32) {
        float t = (threadIdx.x < NW) ? red[threadIdx.x] : 0.f;
        #pragma unroll
        for (int o = 16; o; o >>= 1) t += __shfl_xor_sync(0xffffffffu, t, o);
        if (threadIdx.x == 0) red[0] = t;
    }
    __syncthreads();
    float r = red[0];
    __syncthreads();
    return r;
}

// ------------------------- merged prep kernel -------------------------------
__device__ __forceinline__ void transpose_dev(
    const float* __restrict__ src, __nv_bfloat16* __restrict__ dst,
    int K, int N, int bx, int by, int tx, int ty, float (*t)[33])
{
    int bn = bx * 32, bk = by * 32;
    #pragma unroll
    for (int i = ty; i < 32; i += 8)
        t[i][tx] = src[(size_t)(bk + i) * N + bn + tx];
    __syncthreads();
    #pragma unroll
    for (int i = ty; i < 32; i += 8)
        dst[(size_t)(bn + i) * K + bk + tx] = __float2bfloat16(t[tx][i]);
}

__global__ __launch_bounds__(256) void prep_all(
    const float* __restrict__ h, const float* __restrict__ wqkv,
    const float* __restrict__ wo, const float* __restrict__ proj)
{
    __shared__ float tbuf[32][33];
    int blk = blockIdx.x, tid = threadIdx.x;
    int tx = tid & 31, ty = tid >> 5;
    if (blk < 4096) {                       // conv_h
        int i = blk * 256 + tid;
        float4 v = ((const float4*)h)[i];
        struct alignas(8) BF4 { __nv_bfloat162 a, b; };
        BF4 pk;
        pk.a = __floats2bfloat162_rn(v.x, v.y);
        pk.b = __floats2bfloat162_rn(v.z, v.w);
        ((BF4*)g_hb)[i] = pk;
    } else if (blk < 5120) {                // trans_wqkv: 64 x 16
        int idx = blk - 4096;
        transpose_dev(wqkv, g_wqkvT, 512, 2048, idx & 63, idx >> 6, tx, ty, tbuf);
    } else if (blk < 5376) {                // trans_wo: 16 x 16
        int idx = blk - 5120;
        transpose_dev(wo, g_woT, 512, 512, idx & 15, idx >> 4, tx, ty, tbuf);
    } else {                                // prep_pT
        int i = (blk - 5376) * 256 + tid;
        int d = i >> 8, m = i & 255;
        g_pT[m * 64 + d] = __float2bfloat16(proj[i] * 0.3535533905932738f);
    }
}

// ------------------------- bf16 tensor-core GEMM (cp.async + ldmatrix) ------
#define GPAD 36
#define GEMM_SMEM (2 * 9216 * 4)     // 73,728 B

#define GEMM_PREFETCH(p, buf) do {                                             \
    int _b = (buf) * 9216;                                                     \
    _Pragma("unroll")                                                          \
    for (int _j = 0; _j < 4; _j++) {                                           \
        int _i = tid + _j * 256; int _r = _i >> 3, _c = (_i & 7) * 4;          \
        cpa16(sbase + (uint32_t)(_b + _r * GPAD + _c) * 4,                     \
              A32 + (size_t)(bm + _r) * 256 + (p) * 32 + _c);                  \
        cpa16(sbase + (uint32_t)(_b + 4608 + _r * GPAD + _c) * 4,              \
              B32 + (size_t)(bn + _r) * 256 + (p) * 32 + _c);                  \
    }                                                                          \
} while (0)

template<bool BF16OUT>
__device__ __forceinline__ void gemm_body(
    const __nv_bfloat16* __restrict__ A, const __nv_bfloat16* __restrict__ B,
    float* __restrict__ C, uint32_t* __restrict__ Cb, int Ntot)
{
    extern __shared__ uint32_t sw[];
    uint32_t sbase = smem_u32(sw);
    int tid = threadIdx.x, wid = tid >> 5, lane = tid & 31;
    int wm = wid >> 2, wn = wid & 3;
    int g = lane >> 2, t = lane & 3;
    int bm = blockIdx.y * 128, bn = blockIdx.x * 128;
    const uint32_t* A32 = (const uint32_t*)A;
    const uint32_t* B32 = (const uint32_t*)B;

    // ldmatrix per-lane address components
    int arow = wm * 64 + (lane & 15);           // + i*16
    int akof = (lane >> 4) << 2;                // word 0 or 4
    int brow = wn * 32 + ((lane >> 4) & 1) * 8 + (lane & 7);   // + jj*16
    int bkof = ((lane >> 3) & 1) << 2;

    float acc[4][4][4];
    #pragma unroll
    for (int i = 0; i < 4; i++)
        #pragma unroll
        for (int j = 0; j < 4; j++)
            #pragma unroll
            for (int q = 0; q < 4; q++) acc[i][j][q] = 0.f;

    GEMM_PREFETCH(0, 0);
    CP_COMMIT();

    for (int p = 0; p < 8; p++) {
        CP_WAIT0();
        __syncthreads();
        if (p < 7) { GEMM_PREFETCH(p + 1, (p + 1) & 1); CP_COMMIT(); }
        uint32_t ab = sbase + (uint32_t)((p & 1) * 9216) * 4;
        uint32_t bb = ab + 4608 * 4;
        #pragma unroll
        for (int kk = 0; kk < 4; kk++) {
            uint32_t af[4][4], bf[2][4];
            #pragma unroll
            for (int i = 0; i < 4; i++)
                ldsm4(af[i], ab + (uint32_t)((arow + i * 16) * GPAD + kk * 8 + akof) * 4);
            #pragma unroll
            for (int jj = 0; jj < 2; jj++)
                ldsm4(bf[jj], bb + (uint32_t)((brow + jj * 16) * GPAD + kk * 8 + bkof) * 4);
            #pragma unroll
            for (int i = 0; i < 4; i++)
                #pragma unroll
                for (int j = 0; j < 4; j++)
                    mma16816(acc[i][j], af[i][0], af[i][1], af[i][2], af[i][3],
                             bf[j >> 1][(j & 1) * 2], bf[j >> 1][(j & 1) * 2 + 1]);
        }
    }
    #pragma unroll
    for (int i = 0; i < 4; i++) {
        int row = bm + wm * 64 + i * 16 + g;
        #pragma unroll
        for (int j = 0; j < 4; j++) {
            if (BF16OUT) {
                int widx = (bn >> 1) + wn * 16 + j * 4 + t;
                Cb[(size_t)row * (Ntot >> 1) + widx] = pk2(acc[i][j][0], acc[i][j][1]);
                Cb[(size_t)(row + 8) * (Ntot >> 1) + widx] = pk2(acc[i][j][2], acc[i][j][3]);
            } else {
                int col = bn + wn * 32 + j * 8 + t * 2;
                *(float2*)&C[(size_t)row * Ntot + col] =
                    make_float2(acc[i][j][0], acc[i][j][1]);
                *(float2*)&C[(size_t)(row + 8) * Ntot + col] =
                    make_float2(acc[i][j][2], acc[i][j][3]);
            }
        }
    }
}
__global__ __launch_bounds__(256) void gemm_qkv() {
    gemm_body<true>(g_hb, g_wqkvT, nullptr, (uint32_t*)g_qkvb, 2048);
}
__global__ __launch_bounds__(256) void gemm_wo() {
    gemm_body<true>(g_ai_b, g_woT, nullptr, (uint32_t*)g_yb, 512);
}

// ------------------------- feat2: FAVOR+ via tensor cores -------------------
// (unchanged from R11 — memory-bound near its traffic floor)
#define F_P 0
#define F_X 9216
#define F_V 16128
#define F_STG 18432
#define F_SS 26880
#define FEAT2_SMEM (27392 * 4)     // 109,568 B

__global__ __launch_bounds__(256) void feat2(
    const float* __restrict__ pi0, const float* __restrict__ pi1)
{
    extern __shared__ uint32_t fw[];
    __nv_bfloat16* Vh = (__nv_bfloat16*)(fw + F_V);   // l*72 + d
    float* ss = (float*)(fw + F_SS);
    int tid = threadIdx.x, wid = tid >> 5, lane = tid & 31;
    int wm = wid >> 2, wn = wid & 3;
    int g = lane >> 2, t = lane & 3;
    int l0 = blockIdx.x * 64, bh = blockIdx.y;
    int hh = bh & 7, b = bh >> 3;

    const uint32_t* pTw = (const uint32_t*)g_pT;
    #pragma unroll
    for (int w = 0; w < 32; w++) {
        int idx = tid + w * 256;
        int m = idx >> 5, wd = idx & 31;
        fw[F_P + m * 36 + wd] = pTw[m * 32 + wd];
    }
    const uint32_t* Xg = (const uint32_t*)g_qkvb;
    const __nv_bfloat162 c07 = __float2bfloat162_rn(0.7f);
    #pragma unroll
    for (int w = 0; w < 32; w++) {
        int idx = tid + w * 256;
        int r = idx >> 7, wc = idx & 127;
        uint32_t word = Xg[(size_t)((l0 + r) * 32 + b) * 1024 + hh * 128 + wc];
        if (wc < 96) {
            int seg = wc >> 5, cc = wc & 31;
            if (seg == 2) {
                __nv_bfloat162 tt = *(__nv_bfloat162*)&word;
                tt = __hmul2(tt, c07);
                word = *(uint32_t*)&tt;
            }
            fw[F_X + seg * 2304 + r * 36 + cc] = word;
        } else {
            fw[F_V + r * 36 + (wc - 96)] = word;
        }
    }
    __syncthreads();

    #pragma unroll
    for (int w = 0; w < 16; w++) {
        int idx = tid + w * 256;
        int d = idx >> 6, l = idx & 63;
        g_vt[(size_t)(bh * 64 + d) * 256 + l0 + l] = Vh[l * 72 + d];
    }

    // ===================== seg0: q features =====================
    {
        float acc[2][8][4];
        #pragma unroll
        for (int i = 0; i < 2; i++)
            #pragma unroll
            for (int j = 0; j < 8; j++)
                #pragma unroll
                for (int q = 0; q < 4; q++) acc[i][j][q] = 0.f;
        #pragma unroll
        for (int kk = 0; kk < 4; kk++) {
            uint32_t af[2][4], bf[8][2];
            #pragma unroll
            for (int i = 0; i < 2; i++) {
                int r0 = wm * 32 + i * 16;
                af[i][0] = fw[F_X + (r0 + g    ) * 36 + kk * 8 + t];
                af[i][1] = fw[F_X + (r0 + g + 8) * 36 + kk * 8 + t];
                af[i][2] = fw[F_X + (r0 + g    ) * 36 + kk * 8 + t + 4];
                af[i][3] = fw[F_X + (r0 + g + 8) * 36 + kk * 8 + t + 4];
            }
            #pragma unroll
            for (int j = 0; j < 8; j++) {
                int n0 = wn * 64 + j * 8;
                bf[j][0] = fw[F_P + (n0 + g) * 36 + kk * 8 + t];
                bf[j][1] = fw[F_P + (n0 + g) * 36 + kk * 8 + t + 4];
            }
            #pragma unroll
            for (int i = 0; i < 2; i++)
                #pragma unroll
                for (int j = 0; j < 8; j++)
                    mma16816(acc[i][j], af[i][0], af[i][1], af[i][2], af[i][3],
                             bf[j][0], bf[j][1]);
        }
        float pr[2][2] = {{0.f, 0.f}, {0.f, 0.f}};
        #pragma unroll
        for (int i = 0; i < 2; i++)
            #pragma unroll
            for (int j = 0; j < 8; j++)
                #pragma unroll
                for (int q = 0; q < 4; q++) {
                    float v = fminf(fmaxf(acc[i][j][q], -30.f), 30.f);
                    float e = __expf(v);
                    acc[i][j][q] = e;
                    pr[i][q >> 1] += e + __fdividef(1.f, e);
                }
        #pragma unroll
        for (int i = 0; i < 2; i++)
            #pragma unroll
            for (int hf = 0; hf < 2; hf++) {
                pr[i][hf] += __shfl_xor_sync(0xffffffffu, pr[i][hf], 1);
                pr[i][hf] += __shfl_xor_sync(0xffffffffu, pr[i][hf], 2);
            }
        if (t == 0) {
            #pragma unroll
            for (int i = 0; i < 2; i++) {
                ss[(wm * 32 + i * 16 + g    ) * 4 + wn] = pr[i][0];
                ss[(wm * 32 + i * 16 + g + 8) * 4 + wn] = pr[i][1];
            }
        }
        __syncthreads();
        float invp[2][2];
        #pragma unroll
        for (int i = 0; i < 2; i++)
            #pragma unroll
            for (int hf = 0; hf < 2; hf++) {
                int r = wm * 32 + i * 16 + g + hf * 8;
                float s = ss[r * 4] + ss[r * 4 + 1] + ss[r * 4 + 2] + ss[r * 4 + 3];
                invp[i][hf] = __fdividef(1.f, s);
            }
        uint32_t* dstw = (uint32_t*)g_qf_b;
        #pragma unroll
        for (int i = 0; i < 2; i++) {
            int sr = wm * 32 + i * 16;
            #pragma unroll
            for (int j = 0; j < 8; j++) {
                int wc = wn * 32 + j * 4 + t;
                fw[F_STG + (sr + g    ) * 132 + wc] =
                    pk2(acc[i][j][0] * invp[i][0], acc[i][j][1] * invp[i][0]);
                fw[F_STG + (sr + g + 8) * 132 + wc] =
                    pk2(acc[i][j][2] * invp[i][1], acc[i][j][3] * invp[i][1]);
            }
        }
        __syncthreads();
        #pragma unroll
        for (int w = 0; w < 32; w++) {
            int idx = tid + w * 256;
            int r = idx >> 7, wd = idx & 127;
            dstw[(size_t)(bh * 256 + l0 + r) * 256 + wd] = fw[F_STG + r * 132 + wd];
        }
        __syncthreads();
        #pragma unroll
        for (int i = 0; i < 2; i++) {
            int sr = wm * 32 + i * 16;
            #pragma unroll
            for (int j = 0; j < 8; j++) {
                int wc = wn * 32 + j * 4 + t;
                fw[F_STG + (sr + g    ) * 132 + wc] =
                    pk2(__fdividef(invp[i][0], acc[i][j][0]),
                        __fdividef(invp[i][0], acc[i][j][1]));
                fw[F_STG + (sr + g + 8) * 132 + wc] =
                    pk2(__fdividef(invp[i][1], acc[i][j][2]),
                        __fdividef(invp[i][1], acc[i][j][3]));
            }
        }
        __syncthreads();
        #pragma unroll
        for (int w = 0; w < 32; w++) {
            int idx = tid + w * 256;
            int r = idx >> 7, wd = idx & 127;
            dstw[(size_t)(bh * 256 + l0 + r) * 256 + 128 + wd] = fw[F_STG + r * 132 + wd];
        }
        __syncthreads();
    }

    // ===================== fused seg1+seg2: k features =====================
    {
        float a1[2][8][4], a2[2][8][4];
        #pragma unroll
        for (int i = 0; i < 2; i++)
            #pragma unroll
            for (int j = 0; j < 8; j++)
                #pragma unroll
                for (int q = 0; q < 4; q++) { a1[i][j][q] = 0.f; a2[i][j][q] = 0.f; }
        #pragma unroll
        for (int kk = 0; kk < 4; kk++) {
            uint32_t af1[2][4], af2[2][4], bf[8][2];
            #pragma unroll
            for (int i = 0; i < 2; i++) {
                int r0 = wm * 32 + i * 16;
                af1[i][0] = fw[F_X + 2304 + (r0 + g    ) * 36 + kk * 8 + t];
                af1[i][1] = fw[F_X + 2304 + (r0 + g + 8) * 36 + kk * 8 + t];
                af1[i][2] = fw[F_X + 2304 + (r0 + g    ) * 36 + kk * 8 + t + 4];
                af1[i][3] = fw[F_X + 2304 + (r0 + g + 8) * 36 + kk * 8 + t + 4];
                af2[i][0] = fw[F_X + 4608 + (r0 + g    ) * 36 + kk * 8 + t];
                af2[i][1] = fw[F_X + 4608 + (r0 + g + 8) * 36 + kk * 8 + t];
                af2[i][2] = fw[F_X + 4608 + (r0 + g    ) * 36 + kk * 8 + t + 4];
                af2[i][3] = fw[F_X + 4608 + (r0 + g + 8) * 36 + kk * 8 + t + 4];
            }
            #pragma unroll
            for (int j = 0; j < 8; j++) {
                int n0 = wn * 64 + j * 8;
                bf[j][0] = fw[F_P + (n0 + g) * 36 + kk * 8 + t];
                bf[j][1] = fw[F_P + (n0 + g) * 36 + kk * 8 + t + 4];
            }
            #pragma unroll
            for (int i = 0; i < 2; i++)
                #pragma unroll
                for (int j = 0; j < 8; j++) {
                    mma16816(a1[i][j], af1[i][0], af1[i][1], af1[i][2], af1[i][3],
                             bf[j][0], bf[j][1]);
                    mma16816(a2[i][j], af2[i][0], af2[i][1], af2[i][2], af2[i][3],
                             bf[j][0], bf[j][1]);
                }
        }
        float pr1[2][2] = {{0.f, 0.f}, {0.f, 0.f}};
        float pr2[2][2] = {{0.f, 0.f}, {0.f, 0.f}};
        #pragma unroll
        for (int i = 0; i < 2; i++)
            #pragma unroll
            for (int j = 0; j < 8; j++)
                #pragma unroll
                for (int q = 0; q < 4; q++) {
                    float v1 = fminf(fmaxf(a1[i][j][q], -30.f), 30.f);
                    float e1 = __expf(v1);
                    a1[i][j][q] = e1;
                    pr1[i][q >> 1] += e1 + __fdividef(1.f, e1);
                    float v2 = fminf(fmaxf(a2[i][j][q], -30.f), 30.f);
                    float e2 = __expf(v2);
                    a2[i][j][q] = e2;
                    pr2[i][q >> 1] += e2 + __fdividef(1.f, e2);
                }
        #pragma unroll
        for (int i = 0; i < 2; i++)
            #pragma unroll
            for (int hf = 0; hf < 2; hf++) {
                pr1[i][hf] += __shfl_xor_sync(0xffffffffu, pr1[i][hf], 1);
                pr1[i][hf] += __shfl_xor_sync(0xffffffffu, pr1[i][hf], 2);
                pr2[i][hf] += __shfl_xor_sync(0xffffffffu, pr2[i][hf], 1);
                pr2[i][hf] += __shfl_xor_sync(0xffffffffu, pr2[i][hf], 2);
            }
        if (t == 0) {
            #pragma unroll
            for (int i = 0; i < 2; i++) {
                int ra = wm * 32 + i * 16 + g, rb = ra + 8;
                ss[ra * 4 + wn]       = pr1[i][0];
                ss[rb * 4 + wn]       = pr1[i][1];
                ss[256 + ra * 4 + wn] = pr2[i][0];
                ss[256 + rb * 4 + wn] = pr2[i][1];
            }
        }
        __syncthreads();
        float iv1[2][2], iv2[2][2];
        #pragma unroll
        for (int i = 0; i < 2; i++)
            #pragma unroll
            for (int hf = 0; hf < 2; hf++) {
                int r = wm * 32 + i * 16 + g + hf * 8;
                float s1 = ss[r * 4] + ss[r * 4 + 1] + ss[r * 4 + 2] + ss[r * 4 + 3];
                float s2 = ss[256 + r * 4] + ss[256 + r * 4 + 1]
                         + ss[256 + r * 4 + 2] + ss[256 + r * 4 + 3];
                iv1[i][hf] = __fdividef(pi0[hh * 256 + l0 + r], s1);
                iv2[i][hf] = __fdividef(pi1[hh * 256 + l0 + r], s2);
            }
        uint32_t* dstw = (uint32_t*)g_kf_b;
        #pragma unroll
        for (int i = 0; i < 2; i++) {
            int sr = wm * 32 + i * 16;
            #pragma unroll
            for (int j = 0; j < 8; j++) {
                int wc = wn * 32 + j * 4 + t;
                fw[F_STG + (sr + g    ) * 132 + wc] =
                    pk2(a1[i][j][0] * iv1[i][0] + a2[i][j][0] * iv2[i][0],
                        a1[i][j][1] * iv1[i][0] + a2[i][j][1] * iv2[i][0]);
                fw[F_STG + (sr + g + 8) * 132 + wc] =
                    pk2(a1[i][j][2] * iv1[i][1] + a2[i][j][2] * iv2[i][1],
                        a1[i][j][3] * iv1[i][1] + a2[i][j][3] * iv2[i][1]);
            }
        }
        __syncthreads();
        #pragma unroll
        for (int w = 0; w < 32; w++) {
            int idx = tid + w * 256;
            int r = idx >> 7, wd = idx & 127;
            dstw[(size_t)(bh * 256 + l0 + r) * 256 + wd] = fw[F_STG + r * 132 + wd];
        }
        __syncthreads();
        #pragma unroll
        for (int i = 0; i < 2; i++) {
            int sr = wm * 32 + i * 16;
            #pragma unroll
            for (int j = 0; j < 8; j++) {
                int wc = wn * 32 + j * 4 + t;
                fw[F_STG + (sr + g    ) * 132 + wc] =
                    pk2(__fdividef(iv1[i][0], a1[i][j][0]) + __fdividef(iv2[i][0], a2[i][j][0]),
                        __fdividef(iv1[i][0], a1[i][j][1]) + __fdividef(iv2[i][0], a2[i][j][1]));
                fw[F_STG + (sr + g + 8) * 132 + wc] =
                    pk2(__fdividef(iv1[i][1], a1[i][j][2]) + __fdividef(iv2[i][1], a2[i][j][2]),
                        __fdividef(iv1[i][1], a1[i][j][3]) + __fdividef(iv2[i][1], a2[i][j][3]));
            }
        }
        __syncthreads();
        #pragma unroll
        for (int w = 0; w < 32; w++) {
            int idx = tid + w * 256;
            int r = idx >> 7, wd = idx & 127;
            dstw[(size_t)(bh * 256 + l0 + r) * 256 + 128 + wd] = fw[F_STG + r * 132 + wd];
        }
    }
}

// ------------------------- attn4: flash-style, all-mma, cp.async + ldsm -----
// grid (256, 2): blockIdx.y=0 -> tc=1 blocks first. 8 warps; warp owns 16
// S-rows x 128 cols. Ping-pong Q/K panels, ldmatrix fragments.
#define A4_V 18432
#define A4_D 22784
#define ATTN4_SMEM ((22784 + 128) * 4)    // 91,648 B

#define AT_PREF(p, buf) do {                                                   \
    int _b = (buf) * 9216;                                                      \
    _Pragma("unroll")                                                           \
    for (int _j = 0; _j < 4; _j++) {                                            \
        int _i = tid + _j * 256; int _r = _i >> 3, _c = (_i & 7) * 4;           \
        cpa16(sbase + (uint32_t)(_b + _r * 36 + _c) * 4,                        \
              Qw + (size_t)(bh * 256 + tc * 128 + _r) * 256 + (p) * 32 + _c);   \
        cpa16(sbase + (uint32_t)(_b + 4608 + _r * 36 + _c) * 4,                 \
              Kw + (size_t)(bh * 256 + sc * 128 + _r) * 256 + (p) * 32 + _c);   \
    }                                                                           \
} while (0)

__global__ __launch_bounds__(256) void attn4() {
    extern __shared__ uint32_t aw[];
    uint32_t sbase = smem_u32(aw);
    float* ds = (float*)(aw + A4_D);
    int tid = threadIdx.x, wid = tid >> 5, lane = tid & 31;
    int g = lane >> 2, t = lane & 3;
    int tc = 1 - (int)blockIdx.y, bh = blockIdx.x;
    int hh = bh & 7, b = bh >> 3;
    int lr0 = wid * 16;
    const uint32_t* Qw = (const uint32_t*)g_qf_b;
    const uint32_t* Kw = (const uint32_t*)g_kf_b;
    const uint32_t* Vw = (const uint32_t*)g_vt;

    // ldmatrix lane address components
    int alrow = lr0 + (lane & 15);
    int akof  = (lane >> 4) << 2;
    int brow  = ((lane >> 4) & 1) * 8 + (lane & 7);
    int bkof  = ((lane >> 3) & 1) << 2;

    float out[8][4];
    #pragma unroll
    for (int nd = 0; nd < 8; nd++)
        #pragma unroll
        for (int q = 0; q < 4; q++) out[nd][q] = 0.f;
    float dsum0 = 0.f, dsum1 = 0.f;

    for (int sc = 0; sc <= tc; sc++) {
        __syncthreads();
        #pragma unroll
        for (int _j = 0; _j < 4; _j++) {
            int _i = tid + _j * 256;
            int d = _i >> 4, wd = (_i & 15) * 4;
            cpa16(sbase + (uint32_t)(A4_V + d * 68 + wd) * 4,
                  Vw + (size_t)(bh * 64 + d) * 128 + sc * 64 + wd);
        }
        AT_PREF(0, 0);
        CP_COMMIT();

        float acc[16][4];
        #pragma unroll
        for (int j = 0; j < 16; j++)
            #pragma unroll
            for (int q = 0; q < 4; q++) acc[j][q] = 0.f;

        for (int p = 0; p < 8; p++) {
            CP_WAIT0();
            __syncthreads();
            if (p < 7) { AT_PREF(p + 1, (p + 1) & 1); CP_COMMIT(); }
            uint32_t qb = sbase + (uint32_t)((p & 1) * 9216) * 4;
            uint32_t kb = qb + 4608 * 4;
            #pragma unroll
            for (int kk = 0; kk < 4; kk++) {
                uint32_t aq[4];
                ldsm4(aq, qb + (uint32_t)(alrow * 36 + kk * 8 + akof) * 4);
                #pragma unroll
                for (int jj = 0; jj < 8; jj++) {
                    uint32_t bk[4];
                    ldsm4(bk, kb + (uint32_t)((jj * 16 + brow) * 36 + kk * 8 + bkof) * 4);
                    mma16816(acc[2 * jj],     aq[0], aq[1], aq[2], aq[3], bk[0], bk[1]);
                    mma16816(acc[2 * jj + 1], aq[0], aq[1], aq[2], aq[3], bk[2], bk[3]);
                }
            }
        }
        if (sc == tc) {
            int lr = lr0 + g;
            #pragma unroll
            for (int j = 0; j < 16; j++) {
                int c0 = j * 8 + 2 * t;
                if (c0     > lr)     acc[j][0] = 0.f;
                if (c0 + 1 > lr)     acc[j][1] = 0.f;
                if (c0     > lr + 8) acc[j][2] = 0.f;
                if (c0 + 1 > lr + 8) acc[j][3] = 0.f;
            }
        }
        #pragma unroll
        for (int j = 0; j < 16; j++) {
            dsum0 += acc[j][0] + acc[j][1];
            dsum1 += acc[j][2] + acc[j][3];
        }
        // PV: repack S to bf16 A-fragments, mma vs V^T (ldmatrix for V frags)
        #pragma unroll
        for (int ks = 0; ks < 8; ks++) {
            uint32_t a0 = pk2(acc[2 * ks][0],     acc[2 * ks][1]);
            uint32_t a1 = pk2(acc[2 * ks][2],     acc[2 * ks][3]);
            uint32_t a2 = pk2(acc[2 * ks + 1][0], acc[2 * ks + 1][1]);
            uint32_t a3 = pk2(acc[2 * ks + 1][2], acc[2 * ks + 1][3]);
            #pragma unroll
            for (int nd2 = 0; nd2 < 4; nd2++) {
                uint32_t bv[4];
                ldsm4(bv, sbase + (uint32_t)(A4_V + (nd2 * 16 + brow) * 68 + ks * 8 + bkof) * 4);
                mma16816(out[2 * nd2],     a0, a1, a2, a3, bv[0], bv[1]);
                mma16816(out[2 * nd2 + 1], a0, a1, a2, a3, bv[2], bv[3]);
            }
        }
    }

    dsum0 += __shfl_xor_sync(0xffffffffu, dsum0, 1);
    dsum0 += __shfl_xor_sync(0xffffffffu, dsum0, 2);
    dsum1 += __shfl_xor_sync(0xffffffffu, dsum1, 1);
    dsum1 += __shfl_xor_sync(0xffffffffu, dsum1, 2);
    if (t == 0) { ds[lr0 + g] = dsum0; ds[lr0 + g + 8] = dsum1; }
    __syncthreads();
    int r0 = lr0 + g, r1 = lr0 + g + 8;
    float inv0 = __fdividef(0.125f, ds[r0] + 1e-5f);
    float inv1 = __fdividef(0.125f, ds[r1] + 1e-5f);
    int l0g = tc * 128;
    #pragma unroll
    for (int nd = 0; nd < 8; nd++) {
        int d = nd * 8 + 2 * t;
        __nv_bfloat16* d0 = g_ai_b + (size_t)((l0g + r0) * 32 + b) * 512 + hh * 64 + d;
        __nv_bfloat16* d1 = g_ai_b + (size_t)((l0g + r1) * 32 + b) * 512 + hh * 64 + d;
        *(__nv_bfloat162*)d0 = __floats2bfloat162_rn(out[nd][0] * inv0, out[nd][1] * inv0);
        *(__nv_bfloat162*)d1 = __floats2bfloat162_rn(out[nd][2] * inv1, out[nd][3] * inv1);
    }
}

// ------------------------- residual + LayerNorm ----------------------------
__global__ __launch_bounds__(512) void ln_kernel(
    const float* __restrict__ hin, const float* __restrict__ gamma,
    const float* __restrict__ beta, float* __restrict__ out)
{
    __shared__ float red[32];
    int r = blockIdx.x, j = threadIdx.x;
    float x = __bfloat162float(g_yb[(size_t)r * 512 + j]) + hin[(size_t)r * 512 + j];
    float s1 = block_sum<16>(x, red);
    float mu = s1 * (1.f / 512.f);
    float d = x - mu;
    float s2 = block_sum<16>(d * d, red);
    float rstd = rsqrtf(s2 * (1.f / 512.f) + 1e-5f);
    out[(size_t)r * 512 + j] = d * rstd * gamma[j] + beta[j];
}

// ------------------------- launch ------------------------------------------
extern "C" void kernel_launch(void* const* d_in, const int* in_sizes, int n_in,
                              void* d_out, int out_size) {
    const float* h     = (const float*)d_in[0];
    const float* wqkv  = (const float*)d_in[1];
    const float* wo    = (const float*)d_in[2];
    const float* gamma = (const float*)d_in[3];
    const float* beta  = (const float*)d_in[4];
    const float* pi0   = (const float*)d_in[5];
    const float* pi1   = (const float*)d_in[6];
    const float* proj  = (const float*)d_in[7];

    cudaFuncSetAttribute(gemm_qkv, cudaFuncAttributeMaxDynamicSharedMemorySize, GEMM_SMEM);
    cudaFuncSetAttribute(gemm_wo,  cudaFuncAttributeMaxDynamicSharedMemorySize, GEMM_SMEM);
    cudaFuncSetAttribute(feat2,    cudaFuncAttributeMaxDynamicSharedMemorySize, FEAT2_SMEM);
    cudaFuncSetAttribute(attn4,    cudaFuncAttributeMaxDynamicSharedMemorySize, ATTN4_SMEM);

    prep_all<<<5440, 256>>>(h, wqkv, wo, proj);
    gemm_qkv<<<dim3(16, 64), 256, GEMM_SMEM>>>();
    feat2<<<dim3(4, 256), 256, FEAT2_SMEM>>>(pi0, pi1);
    attn4<<<dim3(256, 2), 256, ATTN4_SMEM>>>();
    gemm_wo<<<dim3(4, 64), 256, GEMM_SMEM>>>();
    ln_kernel<<<8192, 512>>>(h, gamma, beta, (float*)d_out);
}